// round 13
// baseline (speedup 1.0000x reference)
#include <cuda_runtime.h>
#include <cuda_fp16.h>
#include <math.h>
#include <stdint.h>

// Problem constants
#define T_ROWS   8192            // B*N
#define C_DIM    1024
#define H_DIM    16
#define D_DIM    64
#define QKV_N    3072
#define SE_N     2048
#define MLP_DIM  4096
#define FUSED_N  7168
#define INNER    2730
#define INNER_P  2816            // padded (mult of 256)
#define VG_P     5632            // 2*INNER_P (paired layout)
#define OMLP_N   5120            // 1024 (o) + 4096 (mlps)

// ---------------- scratch (static device allocations) ----------------
__device__ __half g_se   [T_ROWS * SE_N];
__device__ __half g_xn   [T_ROWS * C_DIM];
__device__ __half g_qkv  [(size_t)T_ROWS * QKV_N];
__device__ __half g_omlp [(size_t)T_ROWS * OMLP_N];   // [o | mlps]
__device__ __half g_h2   [(size_t)T_ROWS * INNER_P];
__device__ __half g_f    [T_ROWS * C_DIM];
__device__ float  g_gate [T_ROWS * H_DIM];
__device__ float  g_rms  [4 * H_DIM];
// half-converted operands ([K][N] row-major)
__device__ __half g_embt [T_ROWS * C_DIM];
__device__ __half g_Wembh[C_DIM * SE_N];
__device__ __half g_Wfh  [(size_t)C_DIM * FUSED_N];
__device__ __half g_Wminh[(size_t)C_DIM * VG_P];      // paired [vv|g] cols
__device__ float  g_bmin [VG_P];
__device__ __half g_Wmoh [INNER_P * C_DIM];
__device__ __half g_Wcomb[OMLP_N * C_DIM];            // [W_ao ; W_mo]
__device__ float  g_bcomb[C_DIM];

__device__ __forceinline__ uint32_t pack_h2f(float lo, float hi)
{
    uint32_t u;
    asm("cvt.rn.f16x2.f32 %0, %1, %2;" : "=r"(u) : "f"(hi), "f"(lo));
    return u;
}
__device__ __forceinline__ float siluf(float g) { return g / (1.f + __expf(-g)); }

// ---------------- convert kernels (4-wide vectorized) ----------------
__global__ void __launch_bounds__(256) k_cvth4(
    const float* __restrict__ in, __half* __restrict__ out,
    int rows_in, int cols_in, int cols_out)
{
    const int c = (blockIdx.x * 256 + threadIdx.x) * 4;
    const int r = blockIdx.y;
    if (c >= cols_out) return;
    float4 v = make_float4(0.f, 0.f, 0.f, 0.f);
    if (r < rows_in && c < cols_in)
        v = *(const float4*)(in + (size_t)r * cols_in + c);
    *(uint2*)(out + (size_t)r * cols_out + c) =
        make_uint2(pack_h2f(v.x, v.y), pack_h2f(v.z, v.w));
}

__global__ void __launch_bounds__(256) k_cvt_gluW4(
    const float* __restrict__ in, __half* __restrict__ out)
{
    const int c4 = (blockIdx.x * 256 + threadIdx.x) * 4;
    const int r = blockIdx.y;
    if (c4 >= VG_P) return;
    const int p0 = c4 >> 1;                 // even
    float2 vv = make_float2(0.f, 0.f), gg = make_float2(0.f, 0.f);
    if (p0 + 1 < INNER) {
        vv = *(const float2*)(in + (size_t)r * (2 * INNER) + p0);
        gg = *(const float2*)(in + (size_t)r * (2 * INNER) + INNER + p0);
    }
    *(uint2*)(out + (size_t)r * VG_P + c4) =
        make_uint2(pack_h2f(vv.x, gg.x), pack_h2f(vv.y, gg.y));
}

__global__ void __launch_bounds__(256) k_pad_glub(
    const float* __restrict__ in, float* __restrict__ out)
{
    const int c = blockIdx.x * 256 + threadIdx.x;
    if (c >= VG_P) return;
    const int pair = c >> 1, isg = c & 1;
    out[c] = (pair < INNER) ? in[isg ? INNER + pair : pair] : 0.f;
}

__global__ void __launch_bounds__(256) k_addb(
    const float* __restrict__ a, const float* __restrict__ b,
    float* __restrict__ out)
{
    const int c = blockIdx.x * 256 + threadIdx.x;
    if (c < C_DIM) out[c] = a[c] + b[c];
}

// ---------------- fp16 GEMM, 128x256x64, 512 threads, 3-stage cp.async ----
#define BM 128
#define BN 256
#define BK 64
#define NSTG 3
#define AH 72     // BK+8 halves
#define BH 264    // BN+8 halves
#define GSMEM ((NSTG*BM*AH + NSTG*BK*BH) * (int)sizeof(__half))

#define MMA_F16(D, A0,A1,A2,A3, B0,B1)                                        \
    asm volatile(                                                             \
        "mma.sync.aligned.m16n8k16.row.col.f32.f16.f16.f32 "                  \
        "{%0,%1,%2,%3}, {%4,%5,%6,%7}, {%8,%9}, {%0,%1,%2,%3};\n"            \
        : "+f"((D)[0]), "+f"((D)[1]), "+f"((D)[2]), "+f"((D)[3])              \
        : "r"(A0), "r"(A1), "r"(A2), "r"(A3), "r"(B0), "r"(B1))

#define LDSM_X4(R0,R1,R2,R3, ADDR)                                            \
    asm volatile("ldmatrix.sync.aligned.m8n8.x4.shared.b16 "                  \
                 "{%0,%1,%2,%3}, [%4];"                                       \
                 : "=r"(R0), "=r"(R1), "=r"(R2), "=r"(R3) : "r"(ADDR))

#define LDSM_X4T(R0,R1,R2,R3, ADDR)                                           \
    asm volatile("ldmatrix.sync.aligned.m8n8.x4.trans.shared.b16 "            \
                 "{%0,%1,%2,%3}, [%4];"                                       \
                 : "=r"(R0), "=r"(R1), "=r"(R2), "=r"(R3) : "r"(ADDR))

// EPI: 0 none, 1 silu (half), 2 GLU pair -> half at gn/2,
//      3 split: gn<QKV_N plain->C(half), else silu->C2 at gn-QKV_N
template<typename OutT, bool RESID, int EPI>
__global__ void __launch_bounds__(512) tgemm_h(
    const __half* __restrict__ A, int lda,
    const __half* __restrict__ B, int ldb,
    const float* __restrict__ bias,
    const float* __restrict__ R, int ldr,
    OutT* __restrict__ C, int ldc,
    int K,
    __half* __restrict__ C2, int ldc2)
{
    extern __shared__ __half sh[];
    __half* As = sh;                       // [NSTG][BM][AH]
    __half* Bs = sh + NSTG * BM * AH;      // [NSTG][BK][BH]

    const int tid  = threadIdx.x;
    const int warp = tid >> 5, lane = tid & 31;
    const int wm = warp & 3, wn = warp >> 2;     // 4 x 4 warps -> 32x64 tiles
    const int lr = lane >> 2, lc = lane & 3;
    const int bx = blockIdx.x, by = blockIdx.y;

    auto load_tile = [&](int stg, int k0) {
        __half* Asd = As + stg * BM * AH;
        __half* Bsd = Bs + stg * BK * BH;
#pragma unroll
        for (int i = 0; i < 2; i++) {               // 1024 A-chunks of 8 halves
            const int c = tid + i * 512;
            const int r = c >> 3, col = (c & 7) * 8;
            uint32_t d0 = (uint32_t)__cvta_generic_to_shared(Asd + r * AH + col);
            const __half* src = A + (size_t)(by * BM + r) * lda + k0 + col;
            asm volatile("cp.async.cg.shared.global [%0], [%1], 16;\n"
                         :: "r"(d0), "l"(src));
        }
#pragma unroll
        for (int i = 0; i < 4; i++) {               // 2048 B-chunks of 8 halves
            const int c = tid + i * 512;
            const int r = c >> 5, col = (c & 31) * 8;
            uint32_t d1 = (uint32_t)__cvta_generic_to_shared(Bsd + r * BH + col);
            const __half* src = B + (size_t)(k0 + r) * ldb + bx * BN + col;
            asm volatile("cp.async.cg.shared.global [%0], [%1], 16;\n"
                         :: "r"(d1), "l"(src));
        }
        asm volatile("cp.async.commit_group;\n");
    };

    float acc[2][8][4];
#pragma unroll
    for (int mt = 0; mt < 2; mt++)
#pragma unroll
        for (int nt = 0; nt < 8; nt++)
#pragma unroll
            for (int i = 0; i < 4; i++) acc[mt][nt][i] = 0.f;

    const int T = K / BK;
    load_tile(0, 0);
    if (T > 1) load_tile(1, BK);
    asm volatile("cp.async.wait_group 1;\n");
    __syncthreads();

    for (int kt = 0; kt < T; kt++) {
        const int stg = kt % NSTG;
        if (kt + 2 < T) load_tile((kt + 2) % NSTG, (kt + 2) * BK);

        const __half* Asd = As + stg * BM * AH;
        const __half* Bsd = Bs + stg * BK * BH;

#pragma unroll
        for (int kf = 0; kf < 4; kf++) {
            uint32_t af[2][4];
#pragma unroll
            for (int mt = 0; mt < 2; mt++) {
                uint32_t ad = (uint32_t)__cvta_generic_to_shared(
                    Asd + (wm * 32 + mt * 16 + (lane & 15)) * AH +
                    kf * 16 + (lane >> 4) * 8);
                LDSM_X4(af[mt][0], af[mt][1], af[mt][2], af[mt][3], ad);
            }
            uint32_t bf[8][2];
#pragma unroll
            for (int nb = 0; nb < 4; nb++) {
                uint32_t bd = (uint32_t)__cvta_generic_to_shared(
                    Bsd + (kf * 16 + (lane & 15)) * BH +
                    wn * 64 + nb * 16 + (lane >> 4) * 8);
                LDSM_X4T(bf[2*nb][0], bf[2*nb][1], bf[2*nb+1][0], bf[2*nb+1][1], bd);
            }
#pragma unroll
            for (int mt = 0; mt < 2; mt++)
#pragma unroll
                for (int nt = 0; nt < 8; nt++)
                    MMA_F16(acc[mt][nt], af[mt][0], af[mt][1], af[mt][2], af[mt][3],
                            bf[nt][0], bf[nt][1]);
        }
        if (kt + 1 < T) {
            if (kt + 3 <= T) asm volatile("cp.async.wait_group 1;\n");
            else             asm volatile("cp.async.wait_group 0;\n");
            __syncthreads();
        }
    }

#pragma unroll
    for (int mt = 0; mt < 2; mt++) {
        const int gm = by * BM + wm * 32 + mt * 16 + lr;
#pragma unroll
        for (int nt = 0; nt < 8; nt++) {
            const int gn = bx * BN + wn * 64 + nt * 8 + lc * 2;
            const float b0 = bias[gn], b1 = bias[gn + 1];
            float v00 = acc[mt][nt][0] + b0, v01 = acc[mt][nt][1] + b1;
            float v10 = acc[mt][nt][2] + b0, v11 = acc[mt][nt][3] + b1;
            if (EPI == 2) {
                __half* Ch = (__half*)C;
                Ch[(size_t)gm * ldc + (gn >> 1)]       = __float2half(v00 * siluf(v01));
                Ch[(size_t)(gm + 8) * ldc + (gn >> 1)] = __float2half(v10 * siluf(v11));
                continue;
            }
            if (EPI == 3) {
                if (gn < QKV_N) {
                    *(uint32_t*)((__half*)C + (size_t)gm * ldc + gn) = pack_h2f(v00, v01);
                    *(uint32_t*)((__half*)C + (size_t)(gm + 8) * ldc + gn) = pack_h2f(v10, v11);
                } else {
                    const int gn2 = gn - QKV_N;
                    *(uint32_t*)(C2 + (size_t)gm * ldc2 + gn2) =
                        pack_h2f(siluf(v00), siluf(v01));
                    *(uint32_t*)(C2 + (size_t)(gm + 8) * ldc2 + gn2) =
                        pack_h2f(siluf(v10), siluf(v11));
                }
                continue;
            }
            if (RESID) {
                float2 r0 = *(const float2*)(R + (size_t)gm * ldr + gn);
                float2 r1 = *(const float2*)(R + (size_t)(gm + 8) * ldr + gn);
                v00 += r0.x; v01 += r0.y;
                v10 += r1.x; v11 += r1.y;
            }
            if (EPI == 1) {
                v00 = siluf(v00); v01 = siluf(v01);
                v10 = siluf(v10); v11 = siluf(v11);
            }
            if (sizeof(OutT) == 2) {
                *(uint32_t*)((__half*)C + (size_t)gm * ldc + gn) = pack_h2f(v00, v01);
                *(uint32_t*)((__half*)C + (size_t)(gm + 8) * ldc + gn) = pack_h2f(v10, v11);
            } else {
                *(float2*)((float*)C + (size_t)gm * ldc + gn) = make_float2(v00, v01);
                *(float2*)((float*)C + (size_t)(gm + 8) * ldc + gn) = make_float2(v10, v11);
            }
        }
    }
}

// ---------------- block reduce helper ----------------
__device__ __forceinline__ float block_reduce_sum(float v)
{
    __shared__ float shr[32];
    const int lane = threadIdx.x & 31, wid = threadIdx.x >> 5;
#pragma unroll
    for (int o = 16; o > 0; o >>= 1) v += __shfl_xor_sync(0xffffffffu, v, o);
    __syncthreads();
    if (lane == 0) shr[wid] = v;
    __syncthreads();
    const int nw = blockDim.x >> 5;
    float r = (threadIdx.x < nw) ? shr[threadIdx.x] : 0.f;
    if (wid == 0) {
#pragma unroll
        for (int o = 16; o > 0; o >>= 1) r += __shfl_xor_sync(0xffffffffu, r, o);
        if (lane == 0) shr[0] = r;
    }
    __syncthreads();
    return shr[0];
}

// ---------------- LN(x)*(1+scale)+shift -> half ----------------
__global__ void __launch_bounds__(256) k_lnmod(
    const float* __restrict__ x, const float* __restrict__ lnw,
    const float* __restrict__ lnb, const __half* __restrict__ se,
    __half* __restrict__ xn)
{
    const int r = blockIdx.x, tid = threadIdx.x;
    const float4 v = ((const float4*)(x + (size_t)r * C_DIM))[tid];
    float s = v.x + v.y + v.z + v.w;
    s = block_reduce_sum(s);
    const float mu = s * (1.f / 1024.f);
    const float dx0 = v.x - mu, dx1 = v.y - mu, dx2 = v.z - mu, dx3 = v.w - mu;
    float q = dx0 * dx0 + dx1 * dx1 + dx2 * dx2 + dx3 * dx3;
    q = block_reduce_sum(q);
    const float rstd = rsqrtf(q * (1.f / 1024.f) + 1e-5f);
    const float4 w = ((const float4*)lnw)[tid];
    const float4 bb = ((const float4*)lnb)[tid];
    const __half2* sep = (const __half2*)(se + (size_t)r * SE_N);
    const float2 sc01 = __half22float2(sep[tid * 2]);
    const float2 sc23 = __half22float2(sep[tid * 2 + 1]);
    const float2 sf01 = __half22float2(sep[512 + tid * 2]);
    const float2 sf23 = __half22float2(sep[512 + tid * 2 + 1]);
    const float o0 = (dx0 * rstd * w.x + bb.x) * (1.f + sc01.x) + sf01.x;
    const float o1 = (dx1 * rstd * w.y + bb.y) * (1.f + sc01.y) + sf01.y;
    const float o2 = (dx2 * rstd * w.z + bb.z) * (1.f + sc23.x) + sf23.x;
    const float o3 = (dx3 * rstd * w.w + bb.w) * (1.f + sc23.y) + sf23.y;
    ((uint2*)(xn + (size_t)r * C_DIM))[tid] =
        make_uint2(pack_h2f(o0, o1), pack_h2f(o2, o3));
}

// ---------------- per-head LN of q,k (in place in qkv, half) ---------------
__global__ void __launch_bounds__(256) k_qkln(
    __half* __restrict__ qkv,
    const float* __restrict__ qw, const float* __restrict__ qb,
    const float* __restrict__ kw, const float* __restrict__ kb)
{
    const int w = threadIdx.x >> 5, lane = threadIdx.x & 31;
    const int idx = blockIdx.x * 8 + w;
    const int r = idx >> 4, h = idx & 15;
    __half* base = qkv + (size_t)r * QKV_N + h * D_DIM;
#pragma unroll
    for (int part = 0; part < 2; part++) {
        __half* p = base + part * C_DIM;
        float v0 = __half2float(p[lane]), v1 = __half2float(p[lane + 32]);
        float s = v0 + v1;
#pragma unroll
        for (int o = 16; o > 0; o >>= 1) s += __shfl_xor_sync(0xffffffffu, s, o);
        const float mu = s * (1.f / 64.f);
        const float d0 = v0 - mu, d1 = v1 - mu;
        float q = d0 * d0 + d1 * d1;
#pragma unroll
        for (int o = 16; o > 0; o >>= 1) q += __shfl_xor_sync(0xffffffffu, q, o);
        const float rstd = rsqrtf(q * (1.f / 64.f) + 1e-5f);
        const float* ww = part ? kw : qw;
        const float* bb = part ? kb : qb;
        p[lane]      = __float2half(d0 * rstd * ww[lane]      + bb[lane]);
        p[lane + 32] = __float2half(d1 * rstd * ww[lane + 32] + bb[lane + 32]);
    }
}

// ---------------- fp16 mma.sync flash attention (256 q rows, 512 thr) ------
#define QH 72
#define KH 72
#define VH 72
#define QROWS 256
#define ATT_SMEM ((QROWS*QH + 2*64*KH + 2*64*VH) * (int)sizeof(__half))

__global__ void __launch_bounds__(512) k_attn_h(
    const __half* __restrict__ qkv, __half* __restrict__ o)
{
    extern __shared__ __half shh[];
    __half* Qs = shh;                     // [256][QH]
    __half* Ks = Qs + QROWS * QH;         // [2][64][KH]
    __half* Vs = Ks + 2 * 64 * KH;        // [2][64][VH]

    const int qt = blockIdx.x, bh = blockIdx.y;
    const int b = bh >> 4, h = bh & 15;
    const int tid = threadIdx.x;
    const int warp = tid >> 5, lane = tid & 31;
    const int lr = lane >> 2, lc = lane & 3;

    const __half* qbase = qkv + (size_t)(b * 2048 + qt * QROWS) * QKV_N + h * D_DIM;
    const __half2 scl = __float2half2_rn(0.125f);
    for (int it = tid; it < QROWS * 32; it += 512) {
        const int r = it >> 5, c = (it & 31) * 2;
        __half2 v = *(const __half2*)(qbase + (size_t)r * QKV_N + c);
        *(__half2*)(Qs + r * QH + c) = __hmul2(v, scl);
    }

    auto load_kv = [&](int s, int kt) {
        const __half* kb = qkv + (size_t)(b * 2048 + kt * 64) * QKV_N + C_DIM + h * D_DIM;
        const __half* vb = kb + C_DIM;
        __half* Kd = Ks + s * 64 * KH;
        __half* Vd = Vs + s * 64 * VH;
        if (tid < 512) {
            const int it = tid;
            if (it < 512) {
                const int r = it >> 3, c = (it & 7) * 8;
                uint32_t dk = (uint32_t)__cvta_generic_to_shared(Kd + r * KH + c);
                asm volatile("cp.async.cg.shared.global [%0], [%1], 16;\n"
                             :: "r"(dk), "l"(kb + (size_t)r * QKV_N + c));
                uint32_t dv = (uint32_t)__cvta_generic_to_shared(Vd + r * VH + c);
                asm volatile("cp.async.cg.shared.global [%0], [%1], 16;\n"
                             :: "r"(dv), "l"(vb + (size_t)r * QKV_N + c));
            }
        }
        asm volatile("cp.async.commit_group;\n");
    };

    load_kv(0, 0);
    asm volatile("cp.async.wait_group 0;\n");
    __syncthreads();

    uint32_t qa[4][4];
#pragma unroll
    for (int kf = 0; kf < 4; kf++) {
        uint32_t ad = (uint32_t)__cvta_generic_to_shared(
            Qs + (warp * 16 + (lane & 15)) * QH + kf * 16 + (lane >> 4) * 8);
        LDSM_X4(qa[kf][0], qa[kf][1], qa[kf][2], qa[kf][3], ad);
    }

    float m0 = -1e30f, m1 = -1e30f, l0 = 0.f, l1 = 0.f;
    float oa[8][4];
#pragma unroll
    for (int dt = 0; dt < 8; dt++)
#pragma unroll
        for (int i = 0; i < 4; i++) oa[dt][i] = 0.f;

    for (int kt = 0; kt < 32; kt++) {
        const int s = kt & 1;
        if (kt + 1 < 32) load_kv(1 - s, kt + 1);

        const __half* Kd = Ks + s * 64 * KH;
        const __half* Vd = Vs + s * 64 * VH;

        float acc[8][4];
#pragma unroll
        for (int nt = 0; nt < 8; nt++)
#pragma unroll
            for (int i = 0; i < 4; i++) acc[nt][i] = 0.f;

        const int g = lane >> 3;
#pragma unroll
        for (int kf = 0; kf < 4; kf++) {
#pragma unroll
            for (int nb = 0; nb < 4; nb++) {
                uint32_t b0, b1, b2, b3;
                uint32_t bd = (uint32_t)__cvta_generic_to_shared(
                    Kd + (nb * 16 + (g >> 1) * 8 + (lane & 7)) * KH +
                    kf * 16 + (g & 1) * 8);
                LDSM_X4(b0, b1, b2, b3, bd);
                MMA_F16(acc[2*nb],   qa[kf][0], qa[kf][1], qa[kf][2], qa[kf][3], b0, b1);
                MMA_F16(acc[2*nb+1], qa[kf][0], qa[kf][1], qa[kf][2], qa[kf][3], b2, b3);
            }
        }

        float mx0 = -1e30f, mx1 = -1e30f;
#pragma unroll
        for (int nt = 0; nt < 8; nt++) {
            mx0 = fmaxf(mx0, fmaxf(acc[nt][0], acc[nt][1]));
            mx1 = fmaxf(mx1, fmaxf(acc[nt][2], acc[nt][3]));
        }
        mx0 = fmaxf(mx0, __shfl_xor_sync(0xffffffffu, mx0, 1));
        mx0 = fmaxf(mx0, __shfl_xor_sync(0xffffffffu, mx0, 2));
        mx1 = fmaxf(mx1, __shfl_xor_sync(0xffffffffu, mx1, 1));
        mx1 = fmaxf(mx1, __shfl_xor_sync(0xffffffffu, mx1, 2));
        const float mn0 = fmaxf(m0, mx0), mn1 = fmaxf(m1, mx1);
        const float al0 = __expf(m0 - mn0), al1 = __expf(m1 - mn1);
        m0 = mn0; m1 = mn1;
        float rs0 = 0.f, rs1 = 0.f;
#pragma unroll
        for (int nt = 0; nt < 8; nt++) {
            acc[nt][0] = __expf(acc[nt][0] - mn0);
            acc[nt][1] = __expf(acc[nt][1] - mn0);
            acc[nt][2] = __expf(acc[nt][2] - mn1);
            acc[nt][3] = __expf(acc[nt][3] - mn1);
            rs0 += acc[nt][0] + acc[nt][1];
            rs1 += acc[nt][2] + acc[nt][3];
        }
        rs0 += __shfl_xor_sync(0xffffffffu, rs0, 1);
        rs0 += __shfl_xor_sync(0xffffffffu, rs0, 2);
        rs1 += __shfl_xor_sync(0xffffffffu, rs1, 1);
        rs1 += __shfl_xor_sync(0xffffffffu, rs1, 2);
        l0 = l0 * al0 + rs0;
        l1 = l1 * al1 + rs1;
#pragma unroll
        for (int dt = 0; dt < 8; dt++) {
            oa[dt][0] *= al0; oa[dt][1] *= al0;
            oa[dt][2] *= al1; oa[dt][3] *= al1;
        }

#pragma unroll
        for (int c = 0; c < 4; c++) {
            const uint32_t a0 = pack_h2f(acc[2*c][0],   acc[2*c][1]);
            const uint32_t a1 = pack_h2f(acc[2*c][2],   acc[2*c][3]);
            const uint32_t a2 = pack_h2f(acc[2*c+1][0], acc[2*c+1][1]);
            const uint32_t a3 = pack_h2f(acc[2*c+1][2], acc[2*c+1][3]);
#pragma unroll
            for (int nb = 0; nb < 4; nb++) {
                uint32_t v0, v1, v2, v3;
                uint32_t vd = (uint32_t)__cvta_generic_to_shared(
                    Vd + (c * 16 + (lane & 15)) * VH + nb * 16 + (lane >> 4) * 8);
                LDSM_X4T(v0, v1, v2, v3, vd);
                MMA_F16(oa[2*nb],   a0, a1, a2, a3, v0, v1);
                MMA_F16(oa[2*nb+1], a0, a1, a2, a3, v2, v3);
            }
        }

        if (kt + 1 < 32) {
            asm volatile("cp.async.wait_group 0;\n");
            __syncthreads();
        }
    }

    // write into the combined [o|mlps] buffer, stride OMLP_N
    const float i0 = 1.f / l0, i1 = 1.f / l1;
    __half* ob = o + (size_t)(b * 2048 + qt * QROWS + warp * 16 + lr) * OMLP_N + h * D_DIM;
#pragma unroll
    for (int dt = 0; dt < 8; dt++) {
        *(uint32_t*)(ob + dt * 8 + 2 * lc) =
            pack_h2f(oa[dt][0] * i0, oa[dt][1] * i0);
        *(uint32_t*)(ob + 8 * OMLP_N + dt * 8 + 2 * lc) =
            pack_h2f(oa[dt][2] * i1, oa[dt][3] * i1);
    }
}

// ---------------- gate = tanh(x @ W_g + b_g) ----------------
__global__ void __launch_bounds__(256) k_gate(
    const float* __restrict__ x, const float* __restrict__ Wg,
    const float* __restrict__ bg, float* __restrict__ gate)
{
    __shared__ float xs[1024];
    __shared__ float part[16][17];
    const int r = blockIdx.x, tid = threadIdx.x;
    *(float4*)&xs[tid * 4] = ((const float4*)(x + (size_t)r * C_DIM))[tid];
    __syncthreads();
    const int h = tid & 15, seg = tid >> 4;
    float s = 0.f;
#pragma unroll 8
    for (int c = seg * 64; c < seg * 64 + 64; c++) s += xs[c] * Wg[c * 16 + h];
    part[h][seg] = s;
    __syncthreads();
    if (tid < 16) {
        float t = bg[tid];
#pragma unroll
        for (int sg = 0; sg < 16; sg++) t += part[tid][sg];
        gate[(size_t)r * 16 + tid] = tanhf(t);
    }
}

// ---------------- rms[b,h] over (n,d) of f (half) ----------------
__global__ void __launch_bounds__(256) k_rms(const __half* __restrict__ f, float* __restrict__ rms)
{
    const int b = blockIdx.x >> 4, h = blockIdx.x & 15;
    float s = 0.f;
    for (int n = threadIdx.x; n < 2048; n += 256) {
        const __half2* fp = (const __half2*)(f + (size_t)(b * 2048 + n) * C_DIM + h * D_DIM);
#pragma unroll
        for (int d2 = 0; d2 < 32; d2++) {
            const float2 v = __half22float2(fp[d2]);
            s += v.x * v.x + v.y * v.y;
        }
    }
    s = block_reduce_sum(s);
    if (threadIdx.x == 0)
        rms[blockIdx.x] = fmaxf(sqrtf(s * (1.f / 131072.f)), 1e-6f);
}

// ---------------- o = half(o + gate * f / rms), o inside omlp --------------
__global__ void __launch_bounds__(256) k_combine(
    __half* __restrict__ o, const __half* __restrict__ f,
    const float* __restrict__ gate, const float* __restrict__ rms)
{
    const int r = blockIdx.x, tid = threadIdx.x;
    const int h = tid >> 4;
    const float g = gate[(size_t)r * 16 + h] / rms[(r >> 11) * 16 + h];
    __half2* op = (__half2*)(o + (size_t)r * OMLP_N) + tid * 2;
    const __half2* fp = (const __half2*)(f + (size_t)r * C_DIM) + tid * 2;
    const float2 f01 = __half22float2(fp[0]);
    const float2 f23 = __half22float2(fp[1]);
    float2 a = __half22float2(op[0]);
    float2 bq = __half22float2(op[1]);
    a.x += g * f01.x; a.y += g * f01.y;
    bq.x += g * f23.x; bq.y += g * f23.y;
    op[0] = __floats2half2_rn(a.x, a.y);
    op[1] = __floats2half2_rn(bq.x, bq.y);
}

// ---------------- launch ----------------
extern "C" void kernel_launch(void* const* d_in, const int* in_sizes, int n_in,
                              void* d_out, int out_size)
{
    const float* x     = (const float*)d_in[0];
    const float* emb   = (const float*)d_in[1];
    const float* W_emb = (const float*)d_in[2];
    const float* b_emb = (const float*)d_in[3];
    const float* ln_w  = (const float*)d_in[4];
    const float* ln_b  = (const float*)d_in[5];
    const float* W_f   = (const float*)d_in[6];
    const float* b_f   = (const float*)d_in[7];
    const float* qn_w  = (const float*)d_in[8];
    const float* qn_b  = (const float*)d_in[9];
    const float* kn_w  = (const float*)d_in[10];
    const float* kn_b  = (const float*)d_in[11];
    const float* W_ao  = (const float*)d_in[12];
    const float* b_ao  = (const float*)d_in[13];
    const float* W_mo  = (const float*)d_in[14];
    const float* b_mo  = (const float*)d_in[15];
    const float* Wm_in = (const float*)d_in[16];
    const float* bm_in = (const float*)d_in[17];
    const float* Wm_out= (const float*)d_in[18];
    const float* bm_out= (const float*)d_in[19];
    const float* W_g   = (const float*)d_in[20];
    const float* b_g   = (const float*)d_in[21];
    float* out = (float*)d_out;

    float *gate, *rms, *bmin, *bcomb;
    __half *se, *xn, *qkv, *omlp, *h2, *f;
    __half *embt, *Wembh, *Wfh, *Wminh, *Wmoh, *Wcomb;
    cudaGetSymbolAddress((void**)&se,    g_se);
    cudaGetSymbolAddress((void**)&xn,    g_xn);
    cudaGetSymbolAddress((void**)&qkv,   g_qkv);
    cudaGetSymbolAddress((void**)&omlp,  g_omlp);
    cudaGetSymbolAddress((void**)&h2,    g_h2);
    cudaGetSymbolAddress((void**)&f,     g_f);
    cudaGetSymbolAddress((void**)&gate,  g_gate);
    cudaGetSymbolAddress((void**)&rms,   g_rms);
    cudaGetSymbolAddress((void**)&embt,  g_embt);
    cudaGetSymbolAddress((void**)&Wembh, g_Wembh);
    cudaGetSymbolAddress((void**)&Wfh,   g_Wfh);
    cudaGetSymbolAddress((void**)&Wminh, g_Wminh);
    cudaGetSymbolAddress((void**)&bmin,  g_bmin);
    cudaGetSymbolAddress((void**)&Wmoh,  g_Wmoh);
    cudaGetSymbolAddress((void**)&Wcomb, g_Wcomb);
    cudaGetSymbolAddress((void**)&bcomb, g_bcomb);

    cudaFuncSetAttribute(tgemm_h<__half, false, 0>, cudaFuncAttributeMaxDynamicSharedMemorySize, GSMEM);
    cudaFuncSetAttribute(tgemm_h<__half, false, 2>, cudaFuncAttributeMaxDynamicSharedMemorySize, GSMEM);
    cudaFuncSetAttribute(tgemm_h<__half, false, 3>, cudaFuncAttributeMaxDynamicSharedMemorySize, GSMEM);
    cudaFuncSetAttribute(tgemm_h<float, true, 0>,   cudaFuncAttributeMaxDynamicSharedMemorySize, GSMEM);
    cudaFuncSetAttribute(k_attn_h, cudaFuncAttributeMaxDynamicSharedMemorySize, ATT_SMEM);

    const int MB = T_ROWS / 128;  // 64
    dim3 blk(256);
    dim3 gblk(512);

    // ---- operand prep (vectorized 4-wide) ----
    k_cvth4<<<dim3(C_DIM / 1024, T_ROWS), blk>>>(emb, embt, T_ROWS, C_DIM, C_DIM);
    k_cvth4<<<dim3(SE_N / 1024, C_DIM), blk>>>(W_emb, Wembh, C_DIM, SE_N, SE_N);
    k_cvth4<<<dim3(FUSED_N / 1024, C_DIM), blk>>>(W_f, Wfh, C_DIM, FUSED_N, FUSED_N);
    k_cvt_gluW4<<<dim3((VG_P / 4 + 255) / 256, C_DIM), blk>>>(Wm_in, Wminh);
    k_pad_glub<<<dim3((VG_P + 255) / 256), blk>>>(bm_in, bmin);
    k_cvth4<<<dim3(C_DIM / 1024, INNER_P), blk>>>(Wm_out, Wmoh, INNER, C_DIM, C_DIM);
    k_cvth4<<<dim3(C_DIM / 1024, C_DIM), blk>>>(W_ao, Wcomb, C_DIM, C_DIM, C_DIM);
    k_cvth4<<<dim3(C_DIM / 1024, MLP_DIM), blk>>>(W_mo, Wcomb + (size_t)C_DIM * C_DIM,
                                                  MLP_DIM, C_DIM, C_DIM);
    k_addb<<<dim3(C_DIM / 256), blk>>>(b_ao, b_mo, bcomb);

    // se = emb @ W_emb + b_emb  (half out)
    tgemm_h<__half, false, 0><<<dim3(SE_N / 256, MB), gblk, GSMEM>>>(
        embt, C_DIM, Wembh, SE_N, b_emb, nullptr, 0, se, SE_N, C_DIM, nullptr, 0);

    // xn = LN(x)*(1+scale)+shift
    k_lnmod<<<T_ROWS, blk>>>(x, ln_w, ln_b, se, xn);

    // fused: qkv (cols<3072 -> qkv buf) + mlps (silu -> omlp cols [1024:5120))
    tgemm_h<__half, false, 3><<<dim3(FUSED_N / 256, MB), gblk, GSMEM>>>(
        xn, C_DIM, Wfh, FUSED_N, b_f, nullptr, 0, qkv, QKV_N, C_DIM,
        omlp + C_DIM, OMLP_N);

    // per-head LN of q,k in place
    k_qkln<<<T_ROWS * H_DIM / 8, blk>>>(qkv, qn_w, qn_b, kn_w, kn_b);

    // flash attention -> omlp cols [0:1024)   (256 q rows / block)
    k_attn_h<<<dim3(T_ROWS / QROWS / 4, 64), dim3(512), ATT_SMEM>>>(qkv, omlp);

    // h2 = silu(g)*vv fused in GEMM epilogue (paired weights)
    tgemm_h<__half, false, 2><<<dim3(VG_P / 256, MB), gblk, GSMEM>>>(
        qkv, QKV_N, Wminh, VG_P, bmin, nullptr, 0, h2, INNER_P, C_DIM, nullptr, 0);

    // f = h2 @ Wm_out + bm_out  (half out)
    tgemm_h<__half, false, 0><<<dim3(C_DIM / 256, MB), gblk, GSMEM>>>(
        h2, INNER_P, Wmoh, C_DIM, bm_out, nullptr, 0, f, C_DIM, INNER_P, nullptr, 0);

    // gate, rms, combine (updates o-region of omlp in place)
    k_gate<<<T_ROWS, blk>>>(x, W_g, b_g, gate);
    k_rms<<<4 * H_DIM, blk>>>(f, rms);
    k_combine<<<T_ROWS, blk>>>(omlp, f, gate, rms);

    // out = x + [o|mlps] @ [W_ao;W_mo] + (b_ao+b_mo)   — fused K=5120
    tgemm_h<float, true, 0><<<dim3(C_DIM / 256, MB), gblk, GSMEM>>>(
        omlp, OMLP_N, Wcomb, C_DIM, bcomb, x, C_DIM, out, C_DIM, OMLP_N, nullptr, 0);
}

// round 14
// speedup vs baseline: 1.0153x; 1.0153x over previous
#include <cuda_runtime.h>
#include <cuda_fp16.h>
#include <math.h>
#include <stdint.h>

// Problem constants
#define T_ROWS   8192            // B*N
#define C_DIM    1024
#define H_DIM    16
#define D_DIM    64
#define QKV_N    3072
#define SE_N     2048
#define MLP_DIM  4096
#define FUSED_N  7168
#define INNER    2730
#define INNER_P  2816            // padded (mult of 256)
#define VG_P     5632            // 2*INNER_P (paired layout)
#define OMLP_N   5120            // 1024 (o) + 4096 (mlps)

// ---------------- scratch (static device allocations) ----------------
__device__ __half g_se   [T_ROWS * SE_N];
__device__ __half g_xn   [T_ROWS * C_DIM];
__device__ __half g_qkv  [(size_t)T_ROWS * QKV_N];
__device__ __half g_omlp [(size_t)T_ROWS * OMLP_N];   // [o | mlps]
__device__ __half g_h2   [(size_t)T_ROWS * INNER_P];
__device__ __half g_f    [T_ROWS * C_DIM];
__device__ float  g_gate [T_ROWS * H_DIM];
__device__ float  g_rms  [4 * H_DIM];
// half-converted operands ([K][N] row-major)
__device__ __half g_embt [T_ROWS * C_DIM];
__device__ __half g_Wembh[C_DIM * SE_N];
__device__ __half g_Wfh  [(size_t)C_DIM * FUSED_N];
__device__ __half g_Wminh[(size_t)C_DIM * VG_P];      // paired [vv|g] cols
__device__ float  g_bmin [VG_P];
__device__ __half g_Wmoh [INNER_P * C_DIM];
__device__ __half g_Wcomb[OMLP_N * C_DIM];            // [W_ao ; W_mo]
__device__ float  g_bcomb[C_DIM];

__device__ __forceinline__ uint32_t pack_h2f(float lo, float hi)
{
    uint32_t u;
    asm("cvt.rn.f16x2.f32 %0, %1, %2;" : "=r"(u) : "f"(hi), "f"(lo));
    return u;
}
__device__ __forceinline__ float siluf(float g) { return g / (1.f + __expf(-g)); }

// ---------------- convert kernels (4-wide vectorized) ----------------
__global__ void __launch_bounds__(256) k_cvth4(
    const float* __restrict__ in, __half* __restrict__ out,
    int rows_in, int cols_in, int cols_out)
{
    const int c = (blockIdx.x * 256 + threadIdx.x) * 4;
    const int r = blockIdx.y;
    if (c >= cols_out) return;
    float4 v = make_float4(0.f, 0.f, 0.f, 0.f);
    if (r < rows_in && c < cols_in)
        v = *(const float4*)(in + (size_t)r * cols_in + c);
    *(uint2*)(out + (size_t)r * cols_out + c) =
        make_uint2(pack_h2f(v.x, v.y), pack_h2f(v.z, v.w));
}

__global__ void __launch_bounds__(256) k_cvt_gluW4(
    const float* __restrict__ in, __half* __restrict__ out)
{
    const int c4 = (blockIdx.x * 256 + threadIdx.x) * 4;
    const int r = blockIdx.y;
    if (c4 >= VG_P) return;
    const int p0 = c4 >> 1;                 // even
    float2 vv = make_float2(0.f, 0.f), gg = make_float2(0.f, 0.f);
    if (p0 + 1 < INNER) {
        vv = *(const float2*)(in + (size_t)r * (2 * INNER) + p0);
        gg = *(const float2*)(in + (size_t)r * (2 * INNER) + INNER + p0);
    }
    *(uint2*)(out + (size_t)r * VG_P + c4) =
        make_uint2(pack_h2f(vv.x, gg.x), pack_h2f(vv.y, gg.y));
}

__global__ void __launch_bounds__(256) k_pad_glub(
    const float* __restrict__ in, float* __restrict__ out)
{
    const int c = blockIdx.x * 256 + threadIdx.x;
    if (c >= VG_P) return;
    const int pair = c >> 1, isg = c & 1;
    out[c] = (pair < INNER) ? in[isg ? INNER + pair : pair] : 0.f;
}

__global__ void __launch_bounds__(256) k_addb(
    const float* __restrict__ a, const float* __restrict__ b,
    float* __restrict__ out)
{
    const int c = blockIdx.x * 256 + threadIdx.x;
    if (c < C_DIM) out[c] = a[c] + b[c];
}

// ---------------- fp16 GEMM, 128x256x64, 512 threads, 3-stage cp.async ----
#define BM 128
#define BN 256
#define BK 64
#define NSTG 3
#define AH 72     // BK+8 halves
#define BH 264    // BN+8 halves
#define GSMEM ((NSTG*BM*AH + NSTG*BK*BH) * (int)sizeof(__half))

#define MMA_F16(D, A0,A1,A2,A3, B0,B1)                                        \
    asm volatile(                                                             \
        "mma.sync.aligned.m16n8k16.row.col.f32.f16.f16.f32 "                  \
        "{%0,%1,%2,%3}, {%4,%5,%6,%7}, {%8,%9}, {%0,%1,%2,%3};\n"            \
        : "+f"((D)[0]), "+f"((D)[1]), "+f"((D)[2]), "+f"((D)[3])              \
        : "r"(A0), "r"(A1), "r"(A2), "r"(A3), "r"(B0), "r"(B1))

#define LDSM_X4(R0,R1,R2,R3, ADDR)                                            \
    asm volatile("ldmatrix.sync.aligned.m8n8.x4.shared.b16 "                  \
                 "{%0,%1,%2,%3}, [%4];"                                       \
                 : "=r"(R0), "=r"(R1), "=r"(R2), "=r"(R3) : "r"(ADDR))

#define LDSM_X4T(R0,R1,R2,R3, ADDR)                                           \
    asm volatile("ldmatrix.sync.aligned.m8n8.x4.trans.shared.b16 "            \
                 "{%0,%1,%2,%3}, [%4];"                                       \
                 : "=r"(R0), "=r"(R1), "=r"(R2), "=r"(R3) : "r"(ADDR))

// EPI: 0 none, 1 silu (half), 2 GLU pair -> half at gn/2,
//      3 split: gn<QKV_N plain->C(half), else silu->C2 at gn-QKV_N
template<typename OutT, bool RESID, int EPI>
__global__ void __launch_bounds__(512) tgemm_h(
    const __half* __restrict__ A, int lda,
    const __half* __restrict__ B, int ldb,
    const float* __restrict__ bias,
    const float* __restrict__ R, int ldr,
    OutT* __restrict__ C, int ldc,
    int K,
    __half* __restrict__ C2, int ldc2)
{
    extern __shared__ __half sh[];
    __half* As = sh;                       // [NSTG][BM][AH]
    __half* Bs = sh + NSTG * BM * AH;      // [NSTG][BK][BH]

    const int tid  = threadIdx.x;
    const int warp = tid >> 5, lane = tid & 31;
    const int wm = warp & 3, wn = warp >> 2;     // 4 x 4 warps -> 32x64 tiles
    const int lr = lane >> 2, lc = lane & 3;
    const int bx = blockIdx.x, by = blockIdx.y;

    auto load_tile = [&](int stg, int k0) {
        __half* Asd = As + stg * BM * AH;
        __half* Bsd = Bs + stg * BK * BH;
#pragma unroll
        for (int i = 0; i < 2; i++) {               // 1024 A-chunks of 8 halves
            const int c = tid + i * 512;
            const int r = c >> 3, col = (c & 7) * 8;
            uint32_t d0 = (uint32_t)__cvta_generic_to_shared(Asd + r * AH + col);
            const __half* src = A + (size_t)(by * BM + r) * lda + k0 + col;
            asm volatile("cp.async.cg.shared.global [%0], [%1], 16;\n"
                         :: "r"(d0), "l"(src));
        }
#pragma unroll
        for (int i = 0; i < 4; i++) {               // 2048 B-chunks of 8 halves
            const int c = tid + i * 512;
            const int r = c >> 5, col = (c & 31) * 8;
            uint32_t d1 = (uint32_t)__cvta_generic_to_shared(Bsd + r * BH + col);
            const __half* src = B + (size_t)(k0 + r) * ldb + bx * BN + col;
            asm volatile("cp.async.cg.shared.global [%0], [%1], 16;\n"
                         :: "r"(d1), "l"(src));
        }
        asm volatile("cp.async.commit_group;\n");
    };

    float acc[2][8][4];
#pragma unroll
    for (int mt = 0; mt < 2; mt++)
#pragma unroll
        for (int nt = 0; nt < 8; nt++)
#pragma unroll
            for (int i = 0; i < 4; i++) acc[mt][nt][i] = 0.f;

    const int T = K / BK;
    load_tile(0, 0);
    if (T > 1) load_tile(1, BK);
    asm volatile("cp.async.wait_group 1;\n");
    __syncthreads();

    for (int kt = 0; kt < T; kt++) {
        const int stg = kt % NSTG;
        if (kt + 2 < T) load_tile((kt + 2) % NSTG, (kt + 2) * BK);

        const __half* Asd = As + stg * BM * AH;
        const __half* Bsd = Bs + stg * BK * BH;

#pragma unroll
        for (int kf = 0; kf < 4; kf++) {
            uint32_t af[2][4];
#pragma unroll
            for (int mt = 0; mt < 2; mt++) {
                uint32_t ad = (uint32_t)__cvta_generic_to_shared(
                    Asd + (wm * 32 + mt * 16 + (lane & 15)) * AH +
                    kf * 16 + (lane >> 4) * 8);
                LDSM_X4(af[mt][0], af[mt][1], af[mt][2], af[mt][3], ad);
            }
            uint32_t bf[8][2];
#pragma unroll
            for (int nb = 0; nb < 4; nb++) {
                uint32_t bd = (uint32_t)__cvta_generic_to_shared(
                    Bsd + (kf * 16 + (lane & 15)) * BH +
                    wn * 64 + nb * 16 + (lane >> 4) * 8);
                LDSM_X4T(bf[2*nb][0], bf[2*nb][1], bf[2*nb+1][0], bf[2*nb+1][1], bd);
            }
#pragma unroll
            for (int mt = 0; mt < 2; mt++)
#pragma unroll
                for (int nt = 0; nt < 8; nt++)
                    MMA_F16(acc[mt][nt], af[mt][0], af[mt][1], af[mt][2], af[mt][3],
                            bf[nt][0], bf[nt][1]);
        }
        if (kt + 1 < T) {
            if (kt + 3 <= T) asm volatile("cp.async.wait_group 1;\n");
            else             asm volatile("cp.async.wait_group 0;\n");
            __syncthreads();
        }
    }

#pragma unroll
    for (int mt = 0; mt < 2; mt++) {
        const int gm = by * BM + wm * 32 + mt * 16 + lr;
#pragma unroll
        for (int nt = 0; nt < 8; nt++) {
            const int gn = bx * BN + wn * 64 + nt * 8 + lc * 2;
            const float b0 = bias[gn], b1 = bias[gn + 1];
            float v00 = acc[mt][nt][0] + b0, v01 = acc[mt][nt][1] + b1;
            float v10 = acc[mt][nt][2] + b0, v11 = acc[mt][nt][3] + b1;
            if (EPI == 2) {
                __half* Ch = (__half*)C;
                Ch[(size_t)gm * ldc + (gn >> 1)]       = __float2half(v00 * siluf(v01));
                Ch[(size_t)(gm + 8) * ldc + (gn >> 1)] = __float2half(v10 * siluf(v11));
                continue;
            }
            if (EPI == 3) {
                if (gn < QKV_N) {
                    *(uint32_t*)((__half*)C + (size_t)gm * ldc + gn) = pack_h2f(v00, v01);
                    *(uint32_t*)((__half*)C + (size_t)(gm + 8) * ldc + gn) = pack_h2f(v10, v11);
                } else {
                    const int gn2 = gn - QKV_N;
                    *(uint32_t*)(C2 + (size_t)gm * ldc2 + gn2) =
                        pack_h2f(siluf(v00), siluf(v01));
                    *(uint32_t*)(C2 + (size_t)(gm + 8) * ldc2 + gn2) =
                        pack_h2f(siluf(v10), siluf(v11));
                }
                continue;
            }
            if (RESID) {
                float2 r0 = *(const float2*)(R + (size_t)gm * ldr + gn);
                float2 r1 = *(const float2*)(R + (size_t)(gm + 8) * ldr + gn);
                v00 += r0.x; v01 += r0.y;
                v10 += r1.x; v11 += r1.y;
            }
            if (EPI == 1) {
                v00 = siluf(v00); v01 = siluf(v01);
                v10 = siluf(v10); v11 = siluf(v11);
            }
            if (sizeof(OutT) == 2) {
                *(uint32_t*)((__half*)C + (size_t)gm * ldc + gn) = pack_h2f(v00, v01);
                *(uint32_t*)((__half*)C + (size_t)(gm + 8) * ldc + gn) = pack_h2f(v10, v11);
            } else {
                *(float2*)((float*)C + (size_t)gm * ldc + gn) = make_float2(v00, v01);
                *(float2*)((float*)C + (size_t)(gm + 8) * ldc + gn) = make_float2(v10, v11);
            }
        }
    }
}

// ---------------- block reduce helper ----------------
__device__ __forceinline__ float block_reduce_sum(float v)
{
    __shared__ float shr[32];
    const int lane = threadIdx.x & 31, wid = threadIdx.x >> 5;
#pragma unroll
    for (int o = 16; o > 0; o >>= 1) v += __shfl_xor_sync(0xffffffffu, v, o);
    __syncthreads();
    if (lane == 0) shr[wid] = v;
    __syncthreads();
    const int nw = blockDim.x >> 5;
    float r = (threadIdx.x < nw) ? shr[threadIdx.x] : 0.f;
    if (wid == 0) {
#pragma unroll
        for (int o = 16; o > 0; o >>= 1) r += __shfl_xor_sync(0xffffffffu, r, o);
        if (lane == 0) shr[0] = r;
    }
    __syncthreads();
    return shr[0];
}

// ---------------- LN(x)*(1+scale)+shift -> half ----------------
__global__ void __launch_bounds__(256) k_lnmod(
    const float* __restrict__ x, const float* __restrict__ lnw,
    const float* __restrict__ lnb, const __half* __restrict__ se,
    __half* __restrict__ xn)
{
    const int r = blockIdx.x, tid = threadIdx.x;
    const float4 v = ((const float4*)(x + (size_t)r * C_DIM))[tid];
    float s = v.x + v.y + v.z + v.w;
    s = block_reduce_sum(s);
    const float mu = s * (1.f / 1024.f);
    const float dx0 = v.x - mu, dx1 = v.y - mu, dx2 = v.z - mu, dx3 = v.w - mu;
    float q = dx0 * dx0 + dx1 * dx1 + dx2 * dx2 + dx3 * dx3;
    q = block_reduce_sum(q);
    const float rstd = rsqrtf(q * (1.f / 1024.f) + 1e-5f);
    const float4 w = ((const float4*)lnw)[tid];
    const float4 bb = ((const float4*)lnb)[tid];
    const __half2* sep = (const __half2*)(se + (size_t)r * SE_N);
    const float2 sc01 = __half22float2(sep[tid * 2]);
    const float2 sc23 = __half22float2(sep[tid * 2 + 1]);
    const float2 sf01 = __half22float2(sep[512 + tid * 2]);
    const float2 sf23 = __half22float2(sep[512 + tid * 2 + 1]);
    const float o0 = (dx0 * rstd * w.x + bb.x) * (1.f + sc01.x) + sf01.x;
    const float o1 = (dx1 * rstd * w.y + bb.y) * (1.f + sc01.y) + sf01.y;
    const float o2 = (dx2 * rstd * w.z + bb.z) * (1.f + sc23.x) + sf23.x;
    const float o3 = (dx3 * rstd * w.w + bb.w) * (1.f + sc23.y) + sf23.y;
    ((uint2*)(xn + (size_t)r * C_DIM))[tid] =
        make_uint2(pack_h2f(o0, o1), pack_h2f(o2, o3));
}

// ---------------- per-head LN of q,k (in place in qkv, half) ---------------
__global__ void __launch_bounds__(256) k_qkln(
    __half* __restrict__ qkv,
    const float* __restrict__ qw, const float* __restrict__ qb,
    const float* __restrict__ kw, const float* __restrict__ kb)
{
    const int w = threadIdx.x >> 5, lane = threadIdx.x & 31;
    const int idx = blockIdx.x * 8 + w;
    const int r = idx >> 4, h = idx & 15;
    __half* base = qkv + (size_t)r * QKV_N + h * D_DIM;
#pragma unroll
    for (int part = 0; part < 2; part++) {
        __half* p = base + part * C_DIM;
        float v0 = __half2float(p[lane]), v1 = __half2float(p[lane + 32]);
        float s = v0 + v1;
#pragma unroll
        for (int o = 16; o > 0; o >>= 1) s += __shfl_xor_sync(0xffffffffu, s, o);
        const float mu = s * (1.f / 64.f);
        const float d0 = v0 - mu, d1 = v1 - mu;
        float q = d0 * d0 + d1 * d1;
#pragma unroll
        for (int o = 16; o > 0; o >>= 1) q += __shfl_xor_sync(0xffffffffu, q, o);
        const float rstd = rsqrtf(q * (1.f / 64.f) + 1e-5f);
        const float* ww = part ? kw : qw;
        const float* bb = part ? kb : qb;
        p[lane]      = __float2half(d0 * rstd * ww[lane]      + bb[lane]);
        p[lane + 32] = __float2half(d1 * rstd * ww[lane + 32] + bb[lane + 32]);
    }
}

// ---------------- fp16 mma.sync flash attention (3-stage KV pipeline) ------
#define QH 72
#define KH 72
#define VH 72
#define KVSTG 3
#define ATT_SMEM ((128*QH + KVSTG*64*KH + KVSTG*64*VH) * (int)sizeof(__half))

__global__ void __launch_bounds__(256) k_attn_h(
    const __half* __restrict__ qkv, __half* __restrict__ o)
{
    extern __shared__ __half shh[];
    __half* Qs = shh;                      // [128][QH]
    __half* Ks = Qs + 128 * QH;            // [KVSTG][64][KH]
    __half* Vs = Ks + KVSTG * 64 * KH;     // [KVSTG][64][VH]

    const int qt = blockIdx.x, bh = blockIdx.y;
    const int b = bh >> 4, h = bh & 15;
    const int tid = threadIdx.x;
    const int warp = tid >> 5, lane = tid & 31;
    const int lr = lane >> 2, lc = lane & 3;

    const __half* qbase = qkv + (size_t)(b * 2048 + qt * 128) * QKV_N + h * D_DIM;
    const __half2 scl = __float2half2_rn(0.125f);
    for (int it = tid; it < 4096; it += 256) {
        const int r = it >> 5, c = (it & 31) * 2;
        __half2 v = *(const __half2*)(qbase + (size_t)r * QKV_N + c);
        *(__half2*)(Qs + r * QH + c) = __hmul2(v, scl);
    }

    auto load_kv = [&](int s, int kt) {
        const __half* kb = qkv + (size_t)(b * 2048 + kt * 64) * QKV_N + C_DIM + h * D_DIM;
        const __half* vb = kb + C_DIM;
        __half* Kd = Ks + s * 64 * KH;
        __half* Vd = Vs + s * 64 * VH;
        for (int it = tid; it < 512; it += 256) {
            const int r = it >> 3, c = (it & 7) * 8;
            uint32_t dk = (uint32_t)__cvta_generic_to_shared(Kd + r * KH + c);
            asm volatile("cp.async.cg.shared.global [%0], [%1], 16;\n"
                         :: "r"(dk), "l"(kb + (size_t)r * QKV_N + c));
            uint32_t dv = (uint32_t)__cvta_generic_to_shared(Vd + r * VH + c);
            asm volatile("cp.async.cg.shared.global [%0], [%1], 16;\n"
                         :: "r"(dv), "l"(vb + (size_t)r * QKV_N + c));
        }
        asm volatile("cp.async.commit_group;\n");
    };

    load_kv(0, 0);
    load_kv(1, 1);
    asm volatile("cp.async.wait_group 1;\n");
    __syncthreads();

    uint32_t qa[4][4];
#pragma unroll
    for (int kf = 0; kf < 4; kf++) {
        uint32_t ad = (uint32_t)__cvta_generic_to_shared(
            Qs + (warp * 16 + (lane & 15)) * QH + kf * 16 + (lane >> 4) * 8);
        LDSM_X4(qa[kf][0], qa[kf][1], qa[kf][2], qa[kf][3], ad);
    }

    float m0 = -1e30f, m1 = -1e30f, l0 = 0.f, l1 = 0.f;
    float oa[8][4];
#pragma unroll
    for (int dt = 0; dt < 8; dt++)
#pragma unroll
        for (int i = 0; i < 4; i++) oa[dt][i] = 0.f;

    for (int kt = 0; kt < 32; kt++) {
        const int s = kt % KVSTG;
        if (kt + 2 < 32) load_kv((kt + 2) % KVSTG, kt + 2);

        const __half* Kd = Ks + s * 64 * KH;
        const __half* Vd = Vs + s * 64 * VH;

        float acc[8][4];
#pragma unroll
        for (int nt = 0; nt < 8; nt++)
#pragma unroll
            for (int i = 0; i < 4; i++) acc[nt][i] = 0.f;

        const int g = lane >> 3;
#pragma unroll
        for (int kf = 0; kf < 4; kf++) {
#pragma unroll
            for (int nb = 0; nb < 4; nb++) {
                uint32_t b0, b1, b2, b3;
                uint32_t bd = (uint32_t)__cvta_generic_to_shared(
                    Kd + (nb * 16 + (g >> 1) * 8 + (lane & 7)) * KH +
                    kf * 16 + (g & 1) * 8);
                LDSM_X4(b0, b1, b2, b3, bd);
                MMA_F16(acc[2*nb],   qa[kf][0], qa[kf][1], qa[kf][2], qa[kf][3], b0, b1);
                MMA_F16(acc[2*nb+1], qa[kf][0], qa[kf][1], qa[kf][2], qa[kf][3], b2, b3);
            }
        }

        float mx0 = -1e30f, mx1 = -1e30f;
#pragma unroll
        for (int nt = 0; nt < 8; nt++) {
            mx0 = fmaxf(mx0, fmaxf(acc[nt][0], acc[nt][1]));
            mx1 = fmaxf(mx1, fmaxf(acc[nt][2], acc[nt][3]));
        }
        mx0 = fmaxf(mx0, __shfl_xor_sync(0xffffffffu, mx0, 1));
        mx0 = fmaxf(mx0, __shfl_xor_sync(0xffffffffu, mx0, 2));
        mx1 = fmaxf(mx1, __shfl_xor_sync(0xffffffffu, mx1, 1));
        mx1 = fmaxf(mx1, __shfl_xor_sync(0xffffffffu, mx1, 2));
        const float mn0 = fmaxf(m0, mx0), mn1 = fmaxf(m1, mx1);
        const float al0 = __expf(m0 - mn0), al1 = __expf(m1 - mn1);
        m0 = mn0; m1 = mn1;
        float rs0 = 0.f, rs1 = 0.f;
#pragma unroll
        for (int nt = 0; nt < 8; nt++) {
            acc[nt][0] = __expf(acc[nt][0] - mn0);
            acc[nt][1] = __expf(acc[nt][1] - mn0);
            acc[nt][2] = __expf(acc[nt][2] - mn1);
            acc[nt][3] = __expf(acc[nt][3] - mn1);
            rs0 += acc[nt][0] + acc[nt][1];
            rs1 += acc[nt][2] + acc[nt][3];
        }
        rs0 += __shfl_xor_sync(0xffffffffu, rs0, 1);
        rs0 += __shfl_xor_sync(0xffffffffu, rs0, 2);
        rs1 += __shfl_xor_sync(0xffffffffu, rs1, 1);
        rs1 += __shfl_xor_sync(0xffffffffu, rs1, 2);
        l0 = l0 * al0 + rs0;
        l1 = l1 * al1 + rs1;
#pragma unroll
        for (int dt = 0; dt < 8; dt++) {
            oa[dt][0] *= al0; oa[dt][1] *= al0;
            oa[dt][2] *= al1; oa[dt][3] *= al1;
        }

#pragma unroll
        for (int c = 0; c < 4; c++) {
            const uint32_t a0 = pack_h2f(acc[2*c][0],   acc[2*c][1]);
            const uint32_t a1 = pack_h2f(acc[2*c][2],   acc[2*c][3]);
            const uint32_t a2 = pack_h2f(acc[2*c+1][0], acc[2*c+1][1]);
            const uint32_t a3 = pack_h2f(acc[2*c+1][2], acc[2*c+1][3]);
#pragma unroll
            for (int nb = 0; nb < 4; nb++) {
                uint32_t v0, v1, v2, v3;
                uint32_t vd = (uint32_t)__cvta_generic_to_shared(
                    Vd + (c * 16 + (lane & 15)) * VH + nb * 16 + (lane >> 4) * 8);
                LDSM_X4T(v0, v1, v2, v3, vd);
                MMA_F16(oa[2*nb],   a0, a1, a2, a3, v0, v1);
                MMA_F16(oa[2*nb+1], a0, a1, a2, a3, v2, v3);
            }
        }

        if (kt + 1 < 32) {
            // tile kt+1 must be ready; a younger load (kt+2) is outstanding
            // iff kt+2 < 32.
            if (kt + 2 < 32) asm volatile("cp.async.wait_group 1;\n");
            else             asm volatile("cp.async.wait_group 0;\n");
            __syncthreads();
        }
    }

    // write into the combined [o|mlps] buffer, stride OMLP_N
    const float i0 = 1.f / l0, i1 = 1.f / l1;
    __half* ob = o + (size_t)(b * 2048 + qt * 128 + warp * 16 + lr) * OMLP_N + h * D_DIM;
#pragma unroll
    for (int dt = 0; dt < 8; dt++) {
        *(uint32_t*)(ob + dt * 8 + 2 * lc) =
            pack_h2f(oa[dt][0] * i0, oa[dt][1] * i0);
        *(uint32_t*)(ob + 8 * OMLP_N + dt * 8 + 2 * lc) =
            pack_h2f(oa[dt][2] * i1, oa[dt][3] * i1);
    }
}

// ---------------- gate = tanh(x @ W_g + b_g) ----------------
__global__ void __launch_bounds__(256) k_gate(
    const float* __restrict__ x, const float* __restrict__ Wg,
    const float* __restrict__ bg, float* __restrict__ gate)
{
    __shared__ float xs[1024];
    __shared__ float part[16][17];
    const int r = blockIdx.x, tid = threadIdx.x;
    *(float4*)&xs[tid * 4] = ((const float4*)(x + (size_t)r * C_DIM))[tid];
    __syncthreads();
    const int h = tid & 15, seg = tid >> 4;
    float s = 0.f;
#pragma unroll 8
    for (int c = seg * 64; c < seg * 64 + 64; c++) s += xs[c] * Wg[c * 16 + h];
    part[h][seg] = s;
    __syncthreads();
    if (tid < 16) {
        float t = bg[tid];
#pragma unroll
        for (int sg = 0; sg < 16; sg++) t += part[tid][sg];
        gate[(size_t)r * 16 + tid] = tanhf(t);
    }
}

// ---------------- rms[b,h] over (n,d) of f (half) ----------------
__global__ void __launch_bounds__(256) k_rms(const __half* __restrict__ f, float* __restrict__ rms)
{
    const int b = blockIdx.x >> 4, h = blockIdx.x & 15;
    float s = 0.f;
    for (int n = threadIdx.x; n < 2048; n += 256) {
        const __half2* fp = (const __half2*)(f + (size_t)(b * 2048 + n) * C_DIM + h * D_DIM);
#pragma unroll
        for (int d2 = 0; d2 < 32; d2++) {
            const float2 v = __half22float2(fp[d2]);
            s += v.x * v.x + v.y * v.y;
        }
    }
    s = block_reduce_sum(s);
    if (threadIdx.x == 0)
        rms[blockIdx.x] = fmaxf(sqrtf(s * (1.f / 131072.f)), 1e-6f);
}

// ---------------- o = half(o + gate * f / rms), o inside omlp --------------
__global__ void __launch_bounds__(256) k_combine(
    __half* __restrict__ o, const __half* __restrict__ f,
    const float* __restrict__ gate, const float* __restrict__ rms)
{
    const int r = blockIdx.x, tid = threadIdx.x;
    const int h = tid >> 4;
    const float g = gate[(size_t)r * 16 + h] / rms[(r >> 11) * 16 + h];
    __half2* op = (__half2*)(o + (size_t)r * OMLP_N) + tid * 2;
    const __half2* fp = (const __half2*)(f + (size_t)r * C_DIM) + tid * 2;
    const float2 f01 = __half22float2(fp[0]);
    const float2 f23 = __half22float2(fp[1]);
    float2 a = __half22float2(op[0]);
    float2 bq = __half22float2(op[1]);
    a.x += g * f01.x; a.y += g * f01.y;
    bq.x += g * f23.x; bq.y += g * f23.y;
    op[0] = __floats2half2_rn(a.x, a.y);
    op[1] = __floats2half2_rn(bq.x, bq.y);
}

// ---------------- launch ----------------
extern "C" void kernel_launch(void* const* d_in, const int* in_sizes, int n_in,
                              void* d_out, int out_size)
{
    const float* x     = (const float*)d_in[0];
    const float* emb   = (const float*)d_in[1];
    const float* W_emb = (const float*)d_in[2];
    const float* b_emb = (const float*)d_in[3];
    const float* ln_w  = (const float*)d_in[4];
    const float* ln_b  = (const float*)d_in[5];
    const float* W_f   = (const float*)d_in[6];
    const float* b_f   = (const float*)d_in[7];
    const float* qn_w  = (const float*)d_in[8];
    const float* qn_b  = (const float*)d_in[9];
    const float* kn_w  = (const float*)d_in[10];
    const float* kn_b  = (const float*)d_in[11];
    const float* W_ao  = (const float*)d_in[12];
    const float* b_ao  = (const float*)d_in[13];
    const float* W_mo  = (const float*)d_in[14];
    const float* b_mo  = (const float*)d_in[15];
    const float* Wm_in = (const float*)d_in[16];
    const float* bm_in = (const float*)d_in[17];
    const float* Wm_out= (const float*)d_in[18];
    const float* bm_out= (const float*)d_in[19];
    const float* W_g   = (const float*)d_in[20];
    const float* b_g   = (const float*)d_in[21];
    float* out = (float*)d_out;

    float *gate, *rms, *bmin, *bcomb;
    __half *se, *xn, *qkv, *omlp, *h2, *f;
    __half *embt, *Wembh, *Wfh, *Wminh, *Wmoh, *Wcomb;
    cudaGetSymbolAddress((void**)&se,    g_se);
    cudaGetSymbolAddress((void**)&xn,    g_xn);
    cudaGetSymbolAddress((void**)&qkv,   g_qkv);
    cudaGetSymbolAddress((void**)&omlp,  g_omlp);
    cudaGetSymbolAddress((void**)&h2,    g_h2);
    cudaGetSymbolAddress((void**)&f,     g_f);
    cudaGetSymbolAddress((void**)&gate,  g_gate);
    cudaGetSymbolAddress((void**)&rms,   g_rms);
    cudaGetSymbolAddress((void**)&embt,  g_embt);
    cudaGetSymbolAddress((void**)&Wembh, g_Wembh);
    cudaGetSymbolAddress((void**)&Wfh,   g_Wfh);
    cudaGetSymbolAddress((void**)&Wminh, g_Wminh);
    cudaGetSymbolAddress((void**)&bmin,  g_bmin);
    cudaGetSymbolAddress((void**)&Wmoh,  g_Wmoh);
    cudaGetSymbolAddress((void**)&Wcomb, g_Wcomb);
    cudaGetSymbolAddress((void**)&bcomb, g_bcomb);

    cudaFuncSetAttribute(tgemm_h<__half, false, 0>, cudaFuncAttributeMaxDynamicSharedMemorySize, GSMEM);
    cudaFuncSetAttribute(tgemm_h<__half, false, 2>, cudaFuncAttributeMaxDynamicSharedMemorySize, GSMEM);
    cudaFuncSetAttribute(tgemm_h<__half, false, 3>, cudaFuncAttributeMaxDynamicSharedMemorySize, GSMEM);
    cudaFuncSetAttribute(tgemm_h<float, true, 0>,   cudaFuncAttributeMaxDynamicSharedMemorySize, GSMEM);
    cudaFuncSetAttribute(k_attn_h, cudaFuncAttributeMaxDynamicSharedMemorySize, ATT_SMEM);

    const int MB = T_ROWS / 128;  // 64
    dim3 blk(256);
    dim3 gblk(512);

    // ---- operand prep (vectorized 4-wide) ----
    k_cvth4<<<dim3(C_DIM / 1024, T_ROWS), blk>>>(emb, embt, T_ROWS, C_DIM, C_DIM);
    k_cvth4<<<dim3(SE_N / 1024, C_DIM), blk>>>(W_emb, Wembh, C_DIM, SE_N, SE_N);
    k_cvth4<<<dim3(FUSED_N / 1024, C_DIM), blk>>>(W_f, Wfh, C_DIM, FUSED_N, FUSED_N);
    k_cvt_gluW4<<<dim3((VG_P / 4 + 255) / 256, C_DIM), blk>>>(Wm_in, Wminh);
    k_pad_glub<<<dim3((VG_P + 255) / 256), blk>>>(bm_in, bmin);
    k_cvth4<<<dim3(C_DIM / 1024, INNER_P), blk>>>(Wm_out, Wmoh, INNER, C_DIM, C_DIM);
    k_cvth4<<<dim3(C_DIM / 1024, C_DIM), blk>>>(W_ao, Wcomb, C_DIM, C_DIM, C_DIM);
    k_cvth4<<<dim3(C_DIM / 1024, MLP_DIM), blk>>>(W_mo, Wcomb + (size_t)C_DIM * C_DIM,
                                                  MLP_DIM, C_DIM, C_DIM);
    k_addb<<<dim3(C_DIM / 256), blk>>>(b_ao, b_mo, bcomb);

    // se = emb @ W_emb + b_emb  (half out)
    tgemm_h<__half, false, 0><<<dim3(SE_N / 256, MB), gblk, GSMEM>>>(
        embt, C_DIM, Wembh, SE_N, b_emb, nullptr, 0, se, SE_N, C_DIM, nullptr, 0);

    // xn = LN(x)*(1+scale)+shift
    k_lnmod<<<T_ROWS, blk>>>(x, ln_w, ln_b, se, xn);

    // fused: qkv (cols<3072 -> qkv buf) + mlps (silu -> omlp cols [1024:5120))
    tgemm_h<__half, false, 3><<<dim3(FUSED_N / 256, MB), gblk, GSMEM>>>(
        xn, C_DIM, Wfh, FUSED_N, b_f, nullptr, 0, qkv, QKV_N, C_DIM,
        omlp + C_DIM, OMLP_N);

    // per-head LN of q,k in place
    k_qkln<<<T_ROWS * H_DIM / 8, blk>>>(qkv, qn_w, qn_b, kn_w, kn_b);

    // flash attention -> omlp cols [0:1024)
    k_attn_h<<<dim3(16, 64), blk, ATT_SMEM>>>(qkv, omlp);

    // h2 = silu(g)*vv fused in GEMM epilogue (paired weights)
    tgemm_h<__half, false, 2><<<dim3(VG_P / 256, MB), gblk, GSMEM>>>(
        qkv, QKV_N, Wminh, VG_P, bmin, nullptr, 0, h2, INNER_P, C_DIM, nullptr, 0);

    // f = h2 @ Wm_out + bm_out  (half out)
    tgemm_h<__half, false, 0><<<dim3(C_DIM / 256, MB), gblk, GSMEM>>>(
        h2, INNER_P, Wmoh, C_DIM, bm_out, nullptr, 0, f, C_DIM, INNER_P, nullptr, 0);

    // gate, rms, combine (updates o-region of omlp in place)
    k_gate<<<T_ROWS, blk>>>(x, W_g, b_g, gate);
    k_rms<<<4 * H_DIM, blk>>>(f, rms);
    k_combine<<<T_ROWS, blk>>>(omlp, f, gate, rms);

    // out = x + [o|mlps] @ [W_ao;W_mo] + (b_ao+b_mo)   — fused K=5120
    tgemm_h<float, true, 0><<<dim3(C_DIM / 256, MB), gblk, GSMEM>>>(
        omlp, OMLP_N, Wcomb, C_DIM, bcomb, x, C_DIM, out, C_DIM, OMLP_N, nullptr, 0);
}

// round 15
// speedup vs baseline: 1.0458x; 1.0300x over previous
#include <cuda_runtime.h>
#include <cuda_fp16.h>
#include <math.h>
#include <stdint.h>

// Problem constants
#define T_ROWS   8192            // B*N
#define C_DIM    1024
#define H_DIM    16
#define D_DIM    64
#define QKV_N    3072
#define SE_N     2048
#define MLP_DIM  4096
#define FUSED_N  7168
#define INNER    2730
#define INNER_P  2816            // padded (mult of 256)
#define VG_P     5632            // 2*INNER_P (paired layout)
#define OMLP_N   5120            // 1024 (o) + 4096 (mlps)

// ---------------- scratch (static device allocations) ----------------
__device__ __half g_se   [T_ROWS * SE_N];
__device__ __half g_xn   [T_ROWS * C_DIM];
__device__ __half g_qkv  [(size_t)T_ROWS * QKV_N];
__device__ __half g_omlp [(size_t)T_ROWS * OMLP_N];   // [o | mlps]
__device__ __half g_h2   [(size_t)T_ROWS * INNER_P];
__device__ __half g_f    [T_ROWS * C_DIM];
__device__ float  g_gate [T_ROWS * H_DIM];
__device__ float  g_rms  [4 * H_DIM];
// half-converted operands ([K][N] row-major)
__device__ __half g_embt [T_ROWS * C_DIM];
__device__ __half g_Wembh[C_DIM * SE_N];
__device__ __half g_Wfh  [(size_t)C_DIM * FUSED_N];
__device__ __half g_Wminh[(size_t)C_DIM * VG_P];      // paired [vv|g] cols
__device__ float  g_bmin [VG_P];
__device__ __half g_Wmoh [INNER_P * C_DIM];
__device__ __half g_Wcomb[OMLP_N * C_DIM];            // [W_ao ; W_mo]
__device__ float  g_bcomb[C_DIM];

__device__ __forceinline__ uint32_t pack_h2f(float lo, float hi)
{
    uint32_t u;
    asm("cvt.rn.f16x2.f32 %0, %1, %2;" : "=r"(u) : "f"(hi), "f"(lo));
    return u;
}
__device__ __forceinline__ float siluf(float g) { return g / (1.f + __expf(-g)); }

// ---------------- merged convert megakernel ----------------
struct CvtTask { const float* src; __half* dst; int rows_in, cols_in, cols_out, blk_start; };
struct CvtTasks { CvtTask t[6]; };

__global__ void __launch_bounds__(256) k_cvt_all(CvtTasks tasks)
{
    const int bid = blockIdx.x;
    int i = 0;
#pragma unroll
    for (int j = 1; j < 6; j++)
        if (bid >= tasks.t[j].blk_start) i = j;
    const CvtTask tk = tasks.t[i];
    const int rel = bid - tk.blk_start;
    const int cpr = tk.cols_out >> 10;          // 1024-col chunks per row
    const int r = rel / cpr, cc = rel - r * cpr;
    const int c = cc * 1024 + threadIdx.x * 4;
    float4 v = make_float4(0.f, 0.f, 0.f, 0.f);
    if (r < tk.rows_in && c < tk.cols_in)
        v = *(const float4*)(tk.src + (size_t)r * tk.cols_in + c);
    *(uint2*)(tk.dst + (size_t)r * tk.cols_out + c) =
        make_uint2(pack_h2f(v.x, v.y), pack_h2f(v.z, v.w));
}

__global__ void __launch_bounds__(256) k_cvt_gluW4(
    const float* __restrict__ in, __half* __restrict__ out)
{
    const int c4 = (blockIdx.x * 256 + threadIdx.x) * 4;
    const int r = blockIdx.y;
    if (c4 >= VG_P) return;
    const int p0 = c4 >> 1;                 // even
    float2 vv = make_float2(0.f, 0.f), gg = make_float2(0.f, 0.f);
    if (p0 + 1 < INNER) {
        vv = *(const float2*)(in + (size_t)r * (2 * INNER) + p0);
        gg = *(const float2*)(in + (size_t)r * (2 * INNER) + INNER + p0);
    }
    *(uint2*)(out + (size_t)r * VG_P + c4) =
        make_uint2(pack_h2f(vv.x, gg.x), pack_h2f(vv.y, gg.y));
}

// blocks [0,22): pad_glub; blocks [22,26): addb
__global__ void __launch_bounds__(256) k_misc(
    const float* __restrict__ bm_in, float* __restrict__ bmin,
    const float* __restrict__ b_ao, const float* __restrict__ b_mo,
    float* __restrict__ bcomb)
{
    const int bid = blockIdx.x;
    if (bid < 22) {
        const int c = bid * 256 + threadIdx.x;
        if (c >= VG_P) return;
        const int pair = c >> 1, isg = c & 1;
        bmin[c] = (pair < INNER) ? bm_in[isg ? INNER + pair : pair] : 0.f;
    } else {
        const int c = (bid - 22) * 256 + threadIdx.x;
        if (c < C_DIM) bcomb[c] = b_ao[c] + b_mo[c];
    }
}

// ---------------- fp16 GEMM, 128x256x64, 512 threads, 3-stage cp.async ----
#define BM 128
#define BN 256
#define BK 64
#define NSTG 3
#define AH 72     // BK+8 halves
#define BH 264    // BN+8 halves
#define GSMEM ((NSTG*BM*AH + NSTG*BK*BH) * (int)sizeof(__half))

#define MMA_F16(D, A0,A1,A2,A3, B0,B1)                                        \
    asm volatile(                                                             \
        "mma.sync.aligned.m16n8k16.row.col.f32.f16.f16.f32 "                  \
        "{%0,%1,%2,%3}, {%4,%5,%6,%7}, {%8,%9}, {%0,%1,%2,%3};\n"            \
        : "+f"((D)[0]), "+f"((D)[1]), "+f"((D)[2]), "+f"((D)[3])              \
        : "r"(A0), "r"(A1), "r"(A2), "r"(A3), "r"(B0), "r"(B1))

#define LDSM_X4(R0,R1,R2,R3, ADDR)                                            \
    asm volatile("ldmatrix.sync.aligned.m8n8.x4.shared.b16 "                  \
                 "{%0,%1,%2,%3}, [%4];"                                       \
                 : "=r"(R0), "=r"(R1), "=r"(R2), "=r"(R3) : "r"(ADDR))

#define LDSM_X4T(R0,R1,R2,R3, ADDR)                                           \
    asm volatile("ldmatrix.sync.aligned.m8n8.x4.trans.shared.b16 "            \
                 "{%0,%1,%2,%3}, [%4];"                                       \
                 : "=r"(R0), "=r"(R1), "=r"(R2), "=r"(R3) : "r"(ADDR))

// EPI: 0 none, 1 silu (half), 2 GLU pair -> half at gn/2,
//      3 fused-QKV+MLP: bx<4 qLN, bx<8 kLN, bx<12 plain v (all -> C),
//                       bx>=12 silu -> C2 at gn-QKV_N
template<typename OutT, bool RESID, int EPI>
__global__ void __launch_bounds__(512) tgemm_h(
    const __half* __restrict__ A, int lda,
    const __half* __restrict__ B, int ldb,
    const float* __restrict__ bias,
    const float* __restrict__ R, int ldr,
    OutT* __restrict__ C, int ldc,
    int K,
    __half* __restrict__ C2, int ldc2,
    const float* __restrict__ qw, const float* __restrict__ qb,
    const float* __restrict__ kw, const float* __restrict__ kb)
{
    extern __shared__ __half sh[];
    __half* As = sh;                       // [NSTG][BM][AH]
    __half* Bs = sh + NSTG * BM * AH;      // [NSTG][BK][BH]

    const int tid  = threadIdx.x;
    const int warp = tid >> 5, lane = tid & 31;
    const int wm = warp & 3, wn = warp >> 2;     // 4 x 4 warps -> 32x64 tiles
    const int lr = lane >> 2, lc = lane & 3;
    const int bx = blockIdx.x, by = blockIdx.y;

    auto load_tile = [&](int stg, int k0) {
        __half* Asd = As + stg * BM * AH;
        __half* Bsd = Bs + stg * BK * BH;
#pragma unroll
        for (int i = 0; i < 2; i++) {               // 1024 A-chunks of 8 halves
            const int c = tid + i * 512;
            const int r = c >> 3, col = (c & 7) * 8;
            uint32_t d0 = (uint32_t)__cvta_generic_to_shared(Asd + r * AH + col);
            const __half* src = A + (size_t)(by * BM + r) * lda + k0 + col;
            asm volatile("cp.async.cg.shared.global [%0], [%1], 16;\n"
                         :: "r"(d0), "l"(src));
        }
#pragma unroll
        for (int i = 0; i < 4; i++) {               // 2048 B-chunks of 8 halves
            const int c = tid + i * 512;
            const int r = c >> 5, col = (c & 31) * 8;
            uint32_t d1 = (uint32_t)__cvta_generic_to_shared(Bsd + r * BH + col);
            const __half* src = B + (size_t)(k0 + r) * ldb + bx * BN + col;
            asm volatile("cp.async.cg.shared.global [%0], [%1], 16;\n"
                         :: "r"(d1), "l"(src));
        }
        asm volatile("cp.async.commit_group;\n");
    };

    float acc[2][8][4];
#pragma unroll
    for (int mt = 0; mt < 2; mt++)
#pragma unroll
        for (int nt = 0; nt < 8; nt++)
#pragma unroll
            for (int i = 0; i < 4; i++) acc[mt][nt][i] = 0.f;

    const int T = K / BK;
    load_tile(0, 0);
    if (T > 1) load_tile(1, BK);
    asm volatile("cp.async.wait_group 1;\n");
    __syncthreads();

    for (int kt = 0; kt < T; kt++) {
        const int stg = kt % NSTG;
        if (kt + 2 < T) load_tile((kt + 2) % NSTG, (kt + 2) * BK);

        const __half* Asd = As + stg * BM * AH;
        const __half* Bsd = Bs + stg * BK * BH;

#pragma unroll
        for (int kf = 0; kf < 4; kf++) {
            uint32_t af[2][4];
#pragma unroll
            for (int mt = 0; mt < 2; mt++) {
                uint32_t ad = (uint32_t)__cvta_generic_to_shared(
                    Asd + (wm * 32 + mt * 16 + (lane & 15)) * AH +
                    kf * 16 + (lane >> 4) * 8);
                LDSM_X4(af[mt][0], af[mt][1], af[mt][2], af[mt][3], ad);
            }
            uint32_t bf[8][2];
#pragma unroll
            for (int nb = 0; nb < 4; nb++) {
                uint32_t bd = (uint32_t)__cvta_generic_to_shared(
                    Bsd + (kf * 16 + (lane & 15)) * BH +
                    wn * 64 + nb * 16 + (lane >> 4) * 8);
                LDSM_X4T(bf[2*nb][0], bf[2*nb][1], bf[2*nb+1][0], bf[2*nb+1][1], bd);
            }
#pragma unroll
            for (int mt = 0; mt < 2; mt++)
#pragma unroll
                for (int nt = 0; nt < 8; nt++)
                    MMA_F16(acc[mt][nt], af[mt][0], af[mt][1], af[mt][2], af[mt][3],
                            bf[nt][0], bf[nt][1]);
        }
        if (kt + 1 < T) {
            if (kt + 3 <= T) asm volatile("cp.async.wait_group 1;\n");
            else             asm volatile("cp.async.wait_group 0;\n");
            __syncthreads();
        }
    }

    if (EPI == 3) {
        const int region = bx >> 2;        // 0 q, 1 k, 2 v, >=3 mlp
        if (region >= 2) {
#pragma unroll
            for (int mt = 0; mt < 2; mt++) {
                const int gm = by * BM + wm * 32 + mt * 16 + lr;
#pragma unroll
                for (int nt = 0; nt < 8; nt++) {
                    const int gn = bx * BN + wn * 64 + nt * 8 + lc * 2;
                    const float b0 = bias[gn], b1 = bias[gn + 1];
                    const float v00 = acc[mt][nt][0] + b0, v01 = acc[mt][nt][1] + b1;
                    const float v10 = acc[mt][nt][2] + b0, v11 = acc[mt][nt][3] + b1;
                    if (region == 2) {
                        *(uint32_t*)((__half*)C + (size_t)gm * ldc + gn) =
                            pack_h2f(v00, v01);
                        *(uint32_t*)((__half*)C + (size_t)(gm + 8) * ldc + gn) =
                            pack_h2f(v10, v11);
                    } else {
                        const int gn2 = gn - QKV_N;
                        *(uint32_t*)(C2 + (size_t)gm * ldc2 + gn2) =
                            pack_h2f(siluf(v00), siluf(v01));
                        *(uint32_t*)(C2 + (size_t)(gm + 8) * ldc2 + gn2) =
                            pack_h2f(siluf(v10), siluf(v11));
                    }
                }
            }
        } else {
            // per-head LayerNorm fused: warp's 64-col span == one head,
            // each row's 64 values live in one lane-quad (lr fixed, lc 0..3)
            const float* lw = (region == 0) ? qw : kw;
            const float* lb = (region == 0) ? qb : kb;
#pragma unroll
            for (int mt = 0; mt < 2; mt++) {
                const int gm = by * BM + wm * 32 + mt * 16 + lr;
                float v0[16], v1[16];
                float s0 = 0.f, s1 = 0.f;
#pragma unroll
                for (int nt = 0; nt < 8; nt++) {
                    const int gn = bx * BN + wn * 64 + nt * 8 + lc * 2;
                    const float b0 = bias[gn], b1 = bias[gn + 1];
                    v0[2*nt]   = acc[mt][nt][0] + b0;
                    v0[2*nt+1] = acc[mt][nt][1] + b1;
                    v1[2*nt]   = acc[mt][nt][2] + b0;
                    v1[2*nt+1] = acc[mt][nt][3] + b1;
                    s0 += v0[2*nt] + v0[2*nt+1];
                    s1 += v1[2*nt] + v1[2*nt+1];
                }
                s0 += __shfl_xor_sync(0xffffffffu, s0, 1);
                s0 += __shfl_xor_sync(0xffffffffu, s0, 2);
                s1 += __shfl_xor_sync(0xffffffffu, s1, 1);
                s1 += __shfl_xor_sync(0xffffffffu, s1, 2);
                const float mu0 = s0 * (1.f / 64.f), mu1 = s1 * (1.f / 64.f);
                float q0 = 0.f, q1 = 0.f;
#pragma unroll
                for (int i = 0; i < 16; i++) {
                    const float d0 = v0[i] - mu0, d1 = v1[i] - mu1;
                    q0 += d0 * d0; q1 += d1 * d1;
                }
                q0 += __shfl_xor_sync(0xffffffffu, q0, 1);
                q0 += __shfl_xor_sync(0xffffffffu, q0, 2);
                q1 += __shfl_xor_sync(0xffffffffu, q1, 1);
                q1 += __shfl_xor_sync(0xffffffffu, q1, 2);
                const float r0 = rsqrtf(q0 * (1.f / 64.f) + 1e-5f);
                const float r1 = rsqrtf(q1 * (1.f / 64.f) + 1e-5f);
#pragma unroll
                for (int nt = 0; nt < 8; nt++) {
                    const int gn = bx * BN + wn * 64 + nt * 8 + lc * 2;
                    const int d = nt * 8 + lc * 2;
                    const float w0 = lw[d], w1 = lw[d + 1];
                    const float c0 = lb[d], c1 = lb[d + 1];
                    *(uint32_t*)((__half*)C + (size_t)gm * ldc + gn) =
                        pack_h2f((v0[2*nt] - mu0) * r0 * w0 + c0,
                                 (v0[2*nt+1] - mu0) * r0 * w1 + c1);
                    *(uint32_t*)((__half*)C + (size_t)(gm + 8) * ldc + gn) =
                        pack_h2f((v1[2*nt] - mu1) * r1 * w0 + c0,
                                 (v1[2*nt+1] - mu1) * r1 * w1 + c1);
                }
            }
        }
        return;
    }

#pragma unroll
    for (int mt = 0; mt < 2; mt++) {
        const int gm = by * BM + wm * 32 + mt * 16 + lr;
#pragma unroll
        for (int nt = 0; nt < 8; nt++) {
            const int gn = bx * BN + wn * 64 + nt * 8 + lc * 2;
            const float b0 = bias[gn], b1 = bias[gn + 1];
            float v00 = acc[mt][nt][0] + b0, v01 = acc[mt][nt][1] + b1;
            float v10 = acc[mt][nt][2] + b0, v11 = acc[mt][nt][3] + b1;
            if (EPI == 2) {
                __half* Ch = (__half*)C;
                Ch[(size_t)gm * ldc + (gn >> 1)]       = __float2half(v00 * siluf(v01));
                Ch[(size_t)(gm + 8) * ldc + (gn >> 1)] = __float2half(v10 * siluf(v11));
                continue;
            }
            if (RESID) {
                float2 r0 = *(const float2*)(R + (size_t)gm * ldr + gn);
                float2 r1 = *(const float2*)(R + (size_t)(gm + 8) * ldr + gn);
                v00 += r0.x; v01 += r0.y;
                v10 += r1.x; v11 += r1.y;
            }
            if (EPI == 1) {
                v00 = siluf(v00); v01 = siluf(v01);
                v10 = siluf(v10); v11 = siluf(v11);
            }
            if (sizeof(OutT) == 2) {
                *(uint32_t*)((__half*)C + (size_t)gm * ldc + gn) = pack_h2f(v00, v01);
                *(uint32_t*)((__half*)C + (size_t)(gm + 8) * ldc + gn) = pack_h2f(v10, v11);
            } else {
                *(float2*)((float*)C + (size_t)gm * ldc + gn) = make_float2(v00, v01);
                *(float2*)((float*)C + (size_t)(gm + 8) * ldc + gn) = make_float2(v10, v11);
            }
        }
    }
}

// ---------------- block reduce helper ----------------
__device__ __forceinline__ float block_reduce_sum(float v)
{
    __shared__ float shr[32];
    const int lane = threadIdx.x & 31, wid = threadIdx.x >> 5;
#pragma unroll
    for (int o = 16; o > 0; o >>= 1) v += __shfl_xor_sync(0xffffffffu, v, o);
    __syncthreads();
    if (lane == 0) shr[wid] = v;
    __syncthreads();
    const int nw = blockDim.x >> 5;
    float r = (threadIdx.x < nw) ? shr[threadIdx.x] : 0.f;
    if (wid == 0) {
#pragma unroll
        for (int o = 16; o > 0; o >>= 1) r += __shfl_xor_sync(0xffffffffu, r, o);
        if (lane == 0) shr[0] = r;
    }
    __syncthreads();
    return shr[0];
}

// ---------------- LN(x)*(1+scale)+shift -> half ----------------
__global__ void __launch_bounds__(256) k_lnmod(
    const float* __restrict__ x, const float* __restrict__ lnw,
    const float* __restrict__ lnb, const __half* __restrict__ se,
    __half* __restrict__ xn)
{
    const int r = blockIdx.x, tid = threadIdx.x;
    const float4 v = ((const float4*)(x + (size_t)r * C_DIM))[tid];
    float s = v.x + v.y + v.z + v.w;
    s = block_reduce_sum(s);
    const float mu = s * (1.f / 1024.f);
    const float dx0 = v.x - mu, dx1 = v.y - mu, dx2 = v.z - mu, dx3 = v.w - mu;
    float q = dx0 * dx0 + dx1 * dx1 + dx2 * dx2 + dx3 * dx3;
    q = block_reduce_sum(q);
    const float rstd = rsqrtf(q * (1.f / 1024.f) + 1e-5f);
    const float4 w = ((const float4*)lnw)[tid];
    const float4 bb = ((const float4*)lnb)[tid];
    const __half2* sep = (const __half2*)(se + (size_t)r * SE_N);
    const float2 sc01 = __half22float2(sep[tid * 2]);
    const float2 sc23 = __half22float2(sep[tid * 2 + 1]);
    const float2 sf01 = __half22float2(sep[512 + tid * 2]);
    const float2 sf23 = __half22float2(sep[512 + tid * 2 + 1]);
    const float o0 = (dx0 * rstd * w.x + bb.x) * (1.f + sc01.x) + sf01.x;
    const float o1 = (dx1 * rstd * w.y + bb.y) * (1.f + sc01.y) + sf01.y;
    const float o2 = (dx2 * rstd * w.z + bb.z) * (1.f + sc23.x) + sf23.x;
    const float o3 = (dx3 * rstd * w.w + bb.w) * (1.f + sc23.y) + sf23.y;
    ((uint2*)(xn + (size_t)r * C_DIM))[tid] =
        make_uint2(pack_h2f(o0, o1), pack_h2f(o2, o3));
}

// ---------------- fp16 mma.sync flash attention ----------------
#define QH 72
#define KH 72
#define VH 72
#define ATT_SMEM ((128*QH + 2*64*KH + 2*64*VH) * (int)sizeof(__half))

__global__ void __launch_bounds__(256) k_attn_h(
    const __half* __restrict__ qkv, __half* __restrict__ o)
{
    extern __shared__ __half shh[];
    __half* Qs = shh;
    __half* Ks = Qs + 128 * QH;
    __half* Vs = Ks + 2 * 64 * KH;

    const int qt = blockIdx.x, bh = blockIdx.y;
    const int b = bh >> 4, h = bh & 15;
    const int tid = threadIdx.x;
    const int warp = tid >> 5, lane = tid & 31;
    const int lr = lane >> 2, lc = lane & 3;

    const __half* qbase = qkv + (size_t)(b * 2048 + qt * 128) * QKV_N + h * D_DIM;
    const __half2 scl = __float2half2_rn(0.125f);
    for (int it = tid; it < 4096; it += 256) {
        const int r = it >> 5, c = (it & 31) * 2;
        __half2 v = *(const __half2*)(qbase + (size_t)r * QKV_N + c);
        *(__half2*)(Qs + r * QH + c) = __hmul2(v, scl);
    }

    auto load_kv = [&](int s, int kt) {
        const __half* kb = qkv + (size_t)(b * 2048 + kt * 64) * QKV_N + C_DIM + h * D_DIM;
        const __half* vb = kb + C_DIM;
        __half* Kd = Ks + s * 64 * KH;
        __half* Vd = Vs + s * 64 * VH;
        for (int it = tid; it < 512; it += 256) {
            const int r = it >> 3, c = (it & 7) * 8;
            uint32_t dk = (uint32_t)__cvta_generic_to_shared(Kd + r * KH + c);
            asm volatile("cp.async.cg.shared.global [%0], [%1], 16;\n"
                         :: "r"(dk), "l"(kb + (size_t)r * QKV_N + c));
            uint32_t dv = (uint32_t)__cvta_generic_to_shared(Vd + r * VH + c);
            asm volatile("cp.async.cg.shared.global [%0], [%1], 16;\n"
                         :: "r"(dv), "l"(vb + (size_t)r * QKV_N + c));
        }
        asm volatile("cp.async.commit_group;\n");
    };

    load_kv(0, 0);
    asm volatile("cp.async.wait_group 0;\n");
    __syncthreads();

    uint32_t qa[4][4];
#pragma unroll
    for (int kf = 0; kf < 4; kf++) {
        uint32_t ad = (uint32_t)__cvta_generic_to_shared(
            Qs + (warp * 16 + (lane & 15)) * QH + kf * 16 + (lane >> 4) * 8);
        LDSM_X4(qa[kf][0], qa[kf][1], qa[kf][2], qa[kf][3], ad);
    }

    float m0 = -1e30f, m1 = -1e30f, l0 = 0.f, l1 = 0.f;
    float oa[8][4];
#pragma unroll
    for (int dt = 0; dt < 8; dt++)
#pragma unroll
        for (int i = 0; i < 4; i++) oa[dt][i] = 0.f;

    for (int kt = 0; kt < 32; kt++) {
        const int s = kt & 1;
        if (kt + 1 < 32) load_kv(1 - s, kt + 1);

        const __half* Kd = Ks + s * 64 * KH;
        const __half* Vd = Vs + s * 64 * VH;

        float acc[8][4];
#pragma unroll
        for (int nt = 0; nt < 8; nt++)
#pragma unroll
            for (int i = 0; i < 4; i++) acc[nt][i] = 0.f;

        const int g = lane >> 3;
#pragma unroll
        for (int kf = 0; kf < 4; kf++) {
#pragma unroll
            for (int nb = 0; nb < 4; nb++) {
                uint32_t b0, b1, b2, b3;
                uint32_t bd = (uint32_t)__cvta_generic_to_shared(
                    Kd + (nb * 16 + (g >> 1) * 8 + (lane & 7)) * KH +
                    kf * 16 + (g & 1) * 8);
                LDSM_X4(b0, b1, b2, b3, bd);
                MMA_F16(acc[2*nb],   qa[kf][0], qa[kf][1], qa[kf][2], qa[kf][3], b0, b1);
                MMA_F16(acc[2*nb+1], qa[kf][0], qa[kf][1], qa[kf][2], qa[kf][3], b2, b3);
            }
        }

        float mx0 = -1e30f, mx1 = -1e30f;
#pragma unroll
        for (int nt = 0; nt < 8; nt++) {
            mx0 = fmaxf(mx0, fmaxf(acc[nt][0], acc[nt][1]));
            mx1 = fmaxf(mx1, fmaxf(acc[nt][2], acc[nt][3]));
        }
        mx0 = fmaxf(mx0, __shfl_xor_sync(0xffffffffu, mx0, 1));
        mx0 = fmaxf(mx0, __shfl_xor_sync(0xffffffffu, mx0, 2));
        mx1 = fmaxf(mx1, __shfl_xor_sync(0xffffffffu, mx1, 1));
        mx1 = fmaxf(mx1, __shfl_xor_sync(0xffffffffu, mx1, 2));
        const float mn0 = fmaxf(m0, mx0), mn1 = fmaxf(m1, mx1);
        const float al0 = __expf(m0 - mn0), al1 = __expf(m1 - mn1);
        m0 = mn0; m1 = mn1;
        float rs0 = 0.f, rs1 = 0.f;
#pragma unroll
        for (int nt = 0; nt < 8; nt++) {
            acc[nt][0] = __expf(acc[nt][0] - mn0);
            acc[nt][1] = __expf(acc[nt][1] - mn0);
            acc[nt][2] = __expf(acc[nt][2] - mn1);
            acc[nt][3] = __expf(acc[nt][3] - mn1);
            rs0 += acc[nt][0] + acc[nt][1];
            rs1 += acc[nt][2] + acc[nt][3];
        }
        rs0 += __shfl_xor_sync(0xffffffffu, rs0, 1);
        rs0 += __shfl_xor_sync(0xffffffffu, rs0, 2);
        rs1 += __shfl_xor_sync(0xffffffffu, rs1, 1);
        rs1 += __shfl_xor_sync(0xffffffffu, rs1, 2);
        l0 = l0 * al0 + rs0;
        l1 = l1 * al1 + rs1;
#pragma unroll
        for (int dt = 0; dt < 8; dt++) {
            oa[dt][0] *= al0; oa[dt][1] *= al0;
            oa[dt][2] *= al1; oa[dt][3] *= al1;
        }

#pragma unroll
        for (int c = 0; c < 4; c++) {
            const uint32_t a0 = pack_h2f(acc[2*c][0],   acc[2*c][1]);
            const uint32_t a1 = pack_h2f(acc[2*c][2],   acc[2*c][3]);
            const uint32_t a2 = pack_h2f(acc[2*c+1][0], acc[2*c+1][1]);
            const uint32_t a3 = pack_h2f(acc[2*c+1][2], acc[2*c+1][3]);
#pragma unroll
            for (int nb = 0; nb < 4; nb++) {
                uint32_t v0, v1, v2, v3;
                uint32_t vd = (uint32_t)__cvta_generic_to_shared(
                    Vd + (c * 16 + (lane & 15)) * VH + nb * 16 + (lane >> 4) * 8);
                LDSM_X4T(v0, v1, v2, v3, vd);
                MMA_F16(oa[2*nb],   a0, a1, a2, a3, v0, v1);
                MMA_F16(oa[2*nb+1], a0, a1, a2, a3, v2, v3);
            }
        }

        if (kt + 1 < 32) {
            asm volatile("cp.async.wait_group 0;\n");
            __syncthreads();
        }
    }

    const float i0 = 1.f / l0, i1 = 1.f / l1;
    __half* ob = o + (size_t)(b * 2048 + qt * 128 + warp * 16 + lr) * OMLP_N + h * D_DIM;
#pragma unroll
    for (int dt = 0; dt < 8; dt++) {
        *(uint32_t*)(ob + dt * 8 + 2 * lc) =
            pack_h2f(oa[dt][0] * i0, oa[dt][1] * i0);
        *(uint32_t*)(ob + 8 * OMLP_N + dt * 8 + 2 * lc) =
            pack_h2f(oa[dt][2] * i1, oa[dt][3] * i1);
    }
}

// ---------------- gate = tanh(x @ W_g + b_g) ----------------
__global__ void __launch_bounds__(256) k_gate(
    const float* __restrict__ x, const float* __restrict__ Wg,
    const float* __restrict__ bg, float* __restrict__ gate)
{
    __shared__ float xs[1024];
    __shared__ float part[16][17];
    const int r = blockIdx.x, tid = threadIdx.x;
    *(float4*)&xs[tid * 4] = ((const float4*)(x + (size_t)r * C_DIM))[tid];
    __syncthreads();
    const int h = tid & 15, seg = tid >> 4;
    float s = 0.f;
#pragma unroll 8
    for (int c = seg * 64; c < seg * 64 + 64; c++) s += xs[c] * Wg[c * 16 + h];
    part[h][seg] = s;
    __syncthreads();
    if (tid < 16) {
        float t = bg[tid];
#pragma unroll
        for (int sg = 0; sg < 16; sg++) t += part[tid][sg];
        gate[(size_t)r * 16 + tid] = tanhf(t);
    }
}

// ---------------- rms[b,h] over (n,d) of f (half) ----------------
__global__ void __launch_bounds__(256) k_rms(const __half* __restrict__ f, float* __restrict__ rms)
{
    const int b = blockIdx.x >> 4, h = blockIdx.x & 15;
    float s = 0.f;
    for (int n = threadIdx.x; n < 2048; n += 256) {
        const __half2* fp = (const __half2*)(f + (size_t)(b * 2048 + n) * C_DIM + h * D_DIM);
#pragma unroll
        for (int d2 = 0; d2 < 32; d2++) {
            const float2 v = __half22float2(fp[d2]);
            s += v.x * v.x + v.y * v.y;
        }
    }
    s = block_reduce_sum(s);
    if (threadIdx.x == 0)
        rms[blockIdx.x] = fmaxf(sqrtf(s * (1.f / 131072.f)), 1e-6f);
}

// ---------------- o = half(o + gate * f / rms), o inside omlp --------------
__global__ void __launch_bounds__(256) k_combine(
    __half* __restrict__ o, const __half* __restrict__ f,
    const float* __restrict__ gate, const float* __restrict__ rms)
{
    const int r = blockIdx.x, tid = threadIdx.x;
    const int h = tid >> 4;
    const float g = gate[(size_t)r * 16 + h] / rms[(r >> 11) * 16 + h];
    __half2* op = (__half2*)(o + (size_t)r * OMLP_N) + tid * 2;
    const __half2* fp = (const __half2*)(f + (size_t)r * C_DIM) + tid * 2;
    const float2 f01 = __half22float2(fp[0]);
    const float2 f23 = __half22float2(fp[1]);
    float2 a = __half22float2(op[0]);
    float2 bq = __half22float2(op[1]);
    a.x += g * f01.x; a.y += g * f01.y;
    bq.x += g * f23.x; bq.y += g * f23.y;
    op[0] = __floats2half2_rn(a.x, a.y);
    op[1] = __floats2half2_rn(bq.x, bq.y);
}

// ---------------- launch ----------------
extern "C" void kernel_launch(void* const* d_in, const int* in_sizes, int n_in,
                              void* d_out, int out_size)
{
    const float* x     = (const float*)d_in[0];
    const float* emb   = (const float*)d_in[1];
    const float* W_emb = (const float*)d_in[2];
    const float* b_emb = (const float*)d_in[3];
    const float* ln_w  = (const float*)d_in[4];
    const float* ln_b  = (const float*)d_in[5];
    const float* W_f   = (const float*)d_in[6];
    const float* b_f   = (const float*)d_in[7];
    const float* qn_w  = (const float*)d_in[8];
    const float* qn_b  = (const float*)d_in[9];
    const float* kn_w  = (const float*)d_in[10];
    const float* kn_b  = (const float*)d_in[11];
    const float* W_ao  = (const float*)d_in[12];
    const float* b_ao  = (const float*)d_in[13];
    const float* W_mo  = (const float*)d_in[14];
    const float* b_mo  = (const float*)d_in[15];
    const float* Wm_in = (const float*)d_in[16];
    const float* bm_in = (const float*)d_in[17];
    const float* Wm_out= (const float*)d_in[18];
    const float* bm_out= (const float*)d_in[19];
    const float* W_g   = (const float*)d_in[20];
    const float* b_g   = (const float*)d_in[21];
    float* out = (float*)d_out;

    float *gate, *rms, *bmin, *bcomb;
    __half *se, *xn, *qkv, *omlp, *h2, *f;
    __half *embt, *Wembh, *Wfh, *Wminh, *Wmoh, *Wcomb;
    cudaGetSymbolAddress((void**)&se,    g_se);
    cudaGetSymbolAddress((void**)&xn,    g_xn);
    cudaGetSymbolAddress((void**)&qkv,   g_qkv);
    cudaGetSymbolAddress((void**)&omlp,  g_omlp);
    cudaGetSymbolAddress((void**)&h2,    g_h2);
    cudaGetSymbolAddress((void**)&f,     g_f);
    cudaGetSymbolAddress((void**)&gate,  g_gate);
    cudaGetSymbolAddress((void**)&rms,   g_rms);
    cudaGetSymbolAddress((void**)&embt,  g_embt);
    cudaGetSymbolAddress((void**)&Wembh, g_Wembh);
    cudaGetSymbolAddress((void**)&Wfh,   g_Wfh);
    cudaGetSymbolAddress((void**)&Wminh, g_Wminh);
    cudaGetSymbolAddress((void**)&bmin,  g_bmin);
    cudaGetSymbolAddress((void**)&Wmoh,  g_Wmoh);
    cudaGetSymbolAddress((void**)&Wcomb, g_Wcomb);
    cudaGetSymbolAddress((void**)&bcomb, g_bcomb);

    cudaFuncSetAttribute(tgemm_h<__half, false, 0>, cudaFuncAttributeMaxDynamicSharedMemorySize, GSMEM);
    cudaFuncSetAttribute(tgemm_h<__half, false, 2>, cudaFuncAttributeMaxDynamicSharedMemorySize, GSMEM);
    cudaFuncSetAttribute(tgemm_h<__half, false, 3>, cudaFuncAttributeMaxDynamicSharedMemorySize, GSMEM);
    cudaFuncSetAttribute(tgemm_h<float, true, 0>,   cudaFuncAttributeMaxDynamicSharedMemorySize, GSMEM);
    cudaFuncSetAttribute(k_attn_h, cudaFuncAttributeMaxDynamicSharedMemorySize, ATT_SMEM);

    const int MB = T_ROWS / 128;  // 64
    dim3 blk(256);
    dim3 gblk(512);

    // ---- merged operand prep ----
    CvtTasks tasks;
    int bs = 0;
    tasks.t[0] = { emb,    embt,  T_ROWS,  C_DIM,   C_DIM,   bs }; bs += T_ROWS  * (C_DIM   / 1024);
    tasks.t[1] = { W_emb,  Wembh, C_DIM,   SE_N,    SE_N,    bs }; bs += C_DIM   * (SE_N    / 1024);
    tasks.t[2] = { W_f,    Wfh,   C_DIM,   FUSED_N, FUSED_N, bs }; bs += C_DIM   * (FUSED_N / 1024);
    tasks.t[3] = { Wm_out, Wmoh,  INNER,   C_DIM,   C_DIM,   bs }; bs += INNER_P * (C_DIM   / 1024);
    tasks.t[4] = { W_ao,   Wcomb, C_DIM,   C_DIM,   C_DIM,   bs }; bs += C_DIM   * (C_DIM   / 1024);
    tasks.t[5] = { W_mo,   Wcomb + (size_t)C_DIM * C_DIM,
                           MLP_DIM, C_DIM, C_DIM,   bs }; bs += MLP_DIM * (C_DIM / 1024);
    k_cvt_all<<<dim3(bs), blk>>>(tasks);
    k_cvt_gluW4<<<dim3((VG_P / 4 + 255) / 256, C_DIM), blk>>>(Wm_in, Wminh);
    k_misc<<<dim3(26), blk>>>(bm_in, bmin, b_ao, b_mo, bcomb);

    // se = emb @ W_emb + b_emb  (half out)
    tgemm_h<__half, false, 0><<<dim3(SE_N / 256, MB), gblk, GSMEM>>>(
        embt, C_DIM, Wembh, SE_N, b_emb, nullptr, 0, se, SE_N, C_DIM, nullptr, 0,
        nullptr, nullptr, nullptr, nullptr);

    // xn = LN(x)*(1+scale)+shift
    k_lnmod<<<T_ROWS, blk>>>(x, ln_w, ln_b, se, xn);

    // fused: q,k (LN'd) + v -> qkv ; mlps (silu) -> omlp cols [1024:5120)
    tgemm_h<__half, false, 3><<<dim3(FUSED_N / 256, MB), gblk, GSMEM>>>(
        xn, C_DIM, Wfh, FUSED_N, b_f, nullptr, 0, qkv, QKV_N, C_DIM,
        omlp + C_DIM, OMLP_N, qn_w, qn_b, kn_w, kn_b);

    // flash attention -> omlp cols [0:1024)
    k_attn_h<<<dim3(16, 64), blk, ATT_SMEM>>>(qkv, omlp);

    // h2 = silu(g)*vv fused in GEMM epilogue (paired weights)
    tgemm_h<__half, false, 2><<<dim3(VG_P / 256, MB), gblk, GSMEM>>>(
        qkv, QKV_N, Wminh, VG_P, bmin, nullptr, 0, h2, INNER_P, C_DIM, nullptr, 0,
        nullptr, nullptr, nullptr, nullptr);

    // f = h2 @ Wm_out + bm_out  (half out)
    tgemm_h<__half, false, 0><<<dim3(C_DIM / 256, MB), gblk, GSMEM>>>(
        h2, INNER_P, Wmoh, C_DIM, bm_out, nullptr, 0, f, C_DIM, INNER_P, nullptr, 0,
        nullptr, nullptr, nullptr, nullptr);

    // gate, rms, combine (updates o-region of omlp in place)
    k_gate<<<T_ROWS, blk>>>(x, W_g, b_g, gate);
    k_rms<<<4 * H_DIM, blk>>>(f, rms);
    k_combine<<<T_ROWS, blk>>>(omlp, f, gate, rms);

    // out = x + [o|mlps] @ [W_ao;W_mo] + (b_ao+b_mo)   — fused K=5120
    tgemm_h<float, true, 0><<<dim3(C_DIM / 256, MB), gblk, GSMEM>>>(
        omlp, OMLP_N, Wcomb, C_DIM, bcomb, x, C_DIM, out, C_DIM, OMLP_N, nullptr, 0,
        nullptr, nullptr, nullptr, nullptr);
}

// round 16
// speedup vs baseline: 1.1044x; 1.0561x over previous
#include <cuda_runtime.h>
#include <cuda_fp16.h>
#include <math.h>
#include <stdint.h>

// Problem constants
#define T_ROWS   8192            // B*N
#define C_DIM    1024
#define H_DIM    16
#define D_DIM    64
#define QKV_N    3072
#define SE_N     2048
#define MLP_DIM  4096
#define FUSED_N  7168
#define INNER    2730
#define INNER_P  2816            // padded (mult of 128)
#define VG_P     5632            // 2*INNER_P (paired layout)
#define OMLP_N   5120            // 1024 (o) + 4096 (mlps)

// ---------------- scratch (static device allocations) ----------------
__device__ __half g_se   [T_ROWS * SE_N];
__device__ __half g_xn   [T_ROWS * C_DIM];
__device__ __half g_qkv  [(size_t)T_ROWS * QKV_N];
__device__ __half g_omlp [(size_t)T_ROWS * OMLP_N];   // [o | mlps]
__device__ __half g_h2   [(size_t)T_ROWS * INNER_P];
__device__ __half g_f    [T_ROWS * C_DIM];
__device__ float  g_gate [T_ROWS * H_DIM];
__device__ float  g_rms  [4 * H_DIM];
// half-converted operands ([K][N] row-major)
__device__ __half g_embt [T_ROWS * C_DIM];
__device__ __half g_Wembh[C_DIM * SE_N];
__device__ __half g_Wfh  [(size_t)C_DIM * FUSED_N];
__device__ __half g_Wminh[(size_t)C_DIM * VG_P];      // paired [vv|g] cols
__device__ float  g_bmin [VG_P];
__device__ __half g_Wmoh [INNER_P * C_DIM];
__device__ __half g_Wcomb[OMLP_N * C_DIM];            // [W_ao ; W_mo]
__device__ float  g_bcomb[C_DIM];

__device__ __forceinline__ uint32_t pack_h2f(float lo, float hi)
{
    uint32_t u;
    asm("cvt.rn.f16x2.f32 %0, %1, %2;" : "=r"(u) : "f"(hi), "f"(lo));
    return u;
}
__device__ __forceinline__ float siluf(float g) { return g / (1.f + __expf(-g)); }

// ---------------- merged convert megakernel ----------------
struct CvtTask { const float* src; __half* dst; int rows_in, cols_in, cols_out, blk_start; };
struct CvtTasks { CvtTask t[6]; };

__global__ void __launch_bounds__(256) k_cvt_all(CvtTasks tasks)
{
    const int bid = blockIdx.x;
    int i = 0;
#pragma unroll
    for (int j = 1; j < 6; j++)
        if (bid >= tasks.t[j].blk_start) i = j;
    const CvtTask tk = tasks.t[i];
    const int rel = bid - tk.blk_start;
    const int cpr = tk.cols_out >> 10;          // 1024-col chunks per row
    const int r = rel / cpr, cc = rel - r * cpr;
    const int c = cc * 1024 + threadIdx.x * 4;
    float4 v = make_float4(0.f, 0.f, 0.f, 0.f);
    if (r < tk.rows_in && c < tk.cols_in)
        v = *(const float4*)(tk.src + (size_t)r * tk.cols_in + c);
    *(uint2*)(tk.dst + (size_t)r * tk.cols_out + c) =
        make_uint2(pack_h2f(v.x, v.y), pack_h2f(v.z, v.w));
}

__global__ void __launch_bounds__(256) k_cvt_gluW4(
    const float* __restrict__ in, __half* __restrict__ out)
{
    const int c4 = (blockIdx.x * 256 + threadIdx.x) * 4;
    const int r = blockIdx.y;
    if (c4 >= VG_P) return;
    const int p0 = c4 >> 1;                 // even
    float2 vv = make_float2(0.f, 0.f), gg = make_float2(0.f, 0.f);
    if (p0 + 1 < INNER) {
        vv = *(const float2*)(in + (size_t)r * (2 * INNER) + p0);
        gg = *(const float2*)(in + (size_t)r * (2 * INNER) + INNER + p0);
    }
    *(uint2*)(out + (size_t)r * VG_P + c4) =
        make_uint2(pack_h2f(vv.x, gg.x), pack_h2f(vv.y, gg.y));
}

// blocks [0,22): pad_glub; blocks [22,26): addb
__global__ void __launch_bounds__(256) k_misc(
    const float* __restrict__ bm_in, float* __restrict__ bmin,
    const float* __restrict__ b_ao, const float* __restrict__ b_mo,
    float* __restrict__ bcomb)
{
    const int bid = blockIdx.x;
    if (bid < 22) {
        const int c = bid * 256 + threadIdx.x;
        if (c >= VG_P) return;
        const int pair = c >> 1, isg = c & 1;
        bmin[c] = (pair < INNER) ? bm_in[isg ? INNER + pair : pair] : 0.f;
    } else {
        const int c = (bid - 22) * 256 + threadIdx.x;
        if (c < C_DIM) bcomb[c] = b_ao[c] + b_mo[c];
    }
}

// ---------------- fp16 GEMM, 128x128x64, 256 threads, 3-stage cp.async ----
// 105 KB smem -> 2 CTAs/SM (independent barrier domains cover each other)
#define BM 128
#define BN 128
#define BK 64
#define NSTG 3
#define AH 72     // BK+8 halves
#define BH 136    // BN+8 halves
#define GSMEM ((NSTG*BM*AH + NSTG*BK*BH) * (int)sizeof(__half))

#define MMA_F16(D, A0,A1,A2,A3, B0,B1)                                        \
    asm volatile(                                                             \
        "mma.sync.aligned.m16n8k16.row.col.f32.f16.f16.f32 "                  \
        "{%0,%1,%2,%3}, {%4,%5,%6,%7}, {%8,%9}, {%0,%1,%2,%3};\n"            \
        : "+f"((D)[0]), "+f"((D)[1]), "+f"((D)[2]), "+f"((D)[3])              \
        : "r"(A0), "r"(A1), "r"(A2), "r"(A3), "r"(B0), "r"(B1))

#define LDSM_X4(R0,R1,R2,R3, ADDR)                                            \
    asm volatile("ldmatrix.sync.aligned.m8n8.x4.shared.b16 "                  \
                 "{%0,%1,%2,%3}, [%4];"                                       \
                 : "=r"(R0), "=r"(R1), "=r"(R2), "=r"(R3) : "r"(ADDR))

#define LDSM_X4T(R0,R1,R2,R3, ADDR)                                           \
    asm volatile("ldmatrix.sync.aligned.m8n8.x4.trans.shared.b16 "            \
                 "{%0,%1,%2,%3}, [%4];"                                       \
                 : "=r"(R0), "=r"(R1), "=r"(R2), "=r"(R3) : "r"(ADDR))

// EPI: 0 none, 1 silu (half), 2 GLU pair -> half at gn/2,
//      3 fused-QKV+MLP: bx<8 qLN, bx<16 kLN, bx<24 plain v (all -> C),
//                       bx>=24 silu -> C2 at gn-QKV_N
template<typename OutT, bool RESID, int EPI>
__global__ void __launch_bounds__(256, 2) tgemm_h(
    const __half* __restrict__ A, int lda,
    const __half* __restrict__ B, int ldb,
    const float* __restrict__ bias,
    const float* __restrict__ R, int ldr,
    OutT* __restrict__ C, int ldc,
    int K,
    __half* __restrict__ C2, int ldc2,
    const float* __restrict__ qw, const float* __restrict__ qb,
    const float* __restrict__ kw, const float* __restrict__ kb)
{
    extern __shared__ __half sh[];
    __half* As = sh;                       // [NSTG][BM][AH]
    __half* Bs = sh + NSTG * BM * AH;      // [NSTG][BK][BH]

    const int tid  = threadIdx.x;
    const int warp = tid >> 5, lane = tid & 31;
    const int wm = warp & 3, wn = warp >> 2;     // 4 x 2 warps -> 32x64 tiles
    const int lr = lane >> 2, lc = lane & 3;
    const int bx = blockIdx.x, by = blockIdx.y;

    auto load_tile = [&](int stg, int k0) {
        __half* Asd = As + stg * BM * AH;
        __half* Bsd = Bs + stg * BK * BH;
#pragma unroll
        for (int i = 0; i < 4; i++) {               // 1024 A-chunks of 8 halves
            const int c = tid + i * 256;
            const int r = c >> 3, col = (c & 7) * 8;
            uint32_t d0 = (uint32_t)__cvta_generic_to_shared(Asd + r * AH + col);
            const __half* src = A + (size_t)(by * BM + r) * lda + k0 + col;
            asm volatile("cp.async.cg.shared.global [%0], [%1], 16;\n"
                         :: "r"(d0), "l"(src));
        }
#pragma unroll
        for (int i = 0; i < 4; i++) {               // 1024 B-chunks of 8 halves
            const int c = tid + i * 256;
            const int r = c >> 4, col = (c & 15) * 8;
            uint32_t d1 = (uint32_t)__cvta_generic_to_shared(Bsd + r * BH + col);
            const __half* src = B + (size_t)(k0 + r) * ldb + bx * BN + col;
            asm volatile("cp.async.cg.shared.global [%0], [%1], 16;\n"
                         :: "r"(d1), "l"(src));
        }
        asm volatile("cp.async.commit_group;\n");
    };

    float acc[2][8][4];
#pragma unroll
    for (int mt = 0; mt < 2; mt++)
#pragma unroll
        for (int nt = 0; nt < 8; nt++)
#pragma unroll
            for (int i = 0; i < 4; i++) acc[mt][nt][i] = 0.f;

    const int T = K / BK;
    load_tile(0, 0);
    if (T > 1) load_tile(1, BK);
    asm volatile("cp.async.wait_group 1;\n");
    __syncthreads();

    for (int kt = 0; kt < T; kt++) {
        const int stg = kt % NSTG;
        if (kt + 2 < T) load_tile((kt + 2) % NSTG, (kt + 2) * BK);

        const __half* Asd = As + stg * BM * AH;
        const __half* Bsd = Bs + stg * BK * BH;

#pragma unroll
        for (int kf = 0; kf < 4; kf++) {
            uint32_t af[2][4];
#pragma unroll
            for (int mt = 0; mt < 2; mt++) {
                uint32_t ad = (uint32_t)__cvta_generic_to_shared(
                    Asd + (wm * 32 + mt * 16 + (lane & 15)) * AH +
                    kf * 16 + (lane >> 4) * 8);
                LDSM_X4(af[mt][0], af[mt][1], af[mt][2], af[mt][3], ad);
            }
            uint32_t bf[8][2];
#pragma unroll
            for (int nb = 0; nb < 4; nb++) {
                uint32_t bd = (uint32_t)__cvta_generic_to_shared(
                    Bsd + (kf * 16 + (lane & 15)) * BH +
                    wn * 64 + nb * 16 + (lane >> 4) * 8);
                LDSM_X4T(bf[2*nb][0], bf[2*nb][1], bf[2*nb+1][0], bf[2*nb+1][1], bd);
            }
#pragma unroll
            for (int mt = 0; mt < 2; mt++)
#pragma unroll
                for (int nt = 0; nt < 8; nt++)
                    MMA_F16(acc[mt][nt], af[mt][0], af[mt][1], af[mt][2], af[mt][3],
                            bf[nt][0], bf[nt][1]);
        }
        if (kt + 1 < T) {
            if (kt + 3 <= T) asm volatile("cp.async.wait_group 1;\n");
            else             asm volatile("cp.async.wait_group 0;\n");
            __syncthreads();
        }
    }

    if (EPI == 3) {
        const int region = bx >> 3;        // 0 q, 1 k, 2 v, >=3 mlp
        if (region >= 2) {
#pragma unroll
            for (int mt = 0; mt < 2; mt++) {
                const int gm = by * BM + wm * 32 + mt * 16 + lr;
#pragma unroll
                for (int nt = 0; nt < 8; nt++) {
                    const int gn = bx * BN + wn * 64 + nt * 8 + lc * 2;
                    const float b0 = bias[gn], b1 = bias[gn + 1];
                    const float v00 = acc[mt][nt][0] + b0, v01 = acc[mt][nt][1] + b1;
                    const float v10 = acc[mt][nt][2] + b0, v11 = acc[mt][nt][3] + b1;
                    if (region == 2) {
                        *(uint32_t*)((__half*)C + (size_t)gm * ldc + gn) =
                            pack_h2f(v00, v01);
                        *(uint32_t*)((__half*)C + (size_t)(gm + 8) * ldc + gn) =
                            pack_h2f(v10, v11);
                    } else {
                        const int gn2 = gn - QKV_N;
                        *(uint32_t*)(C2 + (size_t)gm * ldc2 + gn2) =
                            pack_h2f(siluf(v00), siluf(v01));
                        *(uint32_t*)(C2 + (size_t)(gm + 8) * ldc2 + gn2) =
                            pack_h2f(siluf(v10), siluf(v11));
                    }
                }
            }
        } else {
            // per-head LayerNorm fused: warp's 64-col span == one head,
            // each row's 64 values live in one lane-quad (lr fixed, lc 0..3)
            const float* lw = (region == 0) ? qw : kw;
            const float* lb = (region == 0) ? qb : kb;
#pragma unroll
            for (int mt = 0; mt < 2; mt++) {
                const int gm = by * BM + wm * 32 + mt * 16 + lr;
                float v0[16], v1[16];
                float s0 = 0.f, s1 = 0.f;
#pragma unroll
                for (int nt = 0; nt < 8; nt++) {
                    const int gn = bx * BN + wn * 64 + nt * 8 + lc * 2;
                    const float b0 = bias[gn], b1 = bias[gn + 1];
                    v0[2*nt]   = acc[mt][nt][0] + b0;
                    v0[2*nt+1] = acc[mt][nt][1] + b1;
                    v1[2*nt]   = acc[mt][nt][2] + b0;
                    v1[2*nt+1] = acc[mt][nt][3] + b1;
                    s0 += v0[2*nt] + v0[2*nt+1];
                    s1 += v1[2*nt] + v1[2*nt+1];
                }
                s0 += __shfl_xor_sync(0xffffffffu, s0, 1);
                s0 += __shfl_xor_sync(0xffffffffu, s0, 2);
                s1 += __shfl_xor_sync(0xffffffffu, s1, 1);
                s1 += __shfl_xor_sync(0xffffffffu, s1, 2);
                const float mu0 = s0 * (1.f / 64.f), mu1 = s1 * (1.f / 64.f);
                float q0 = 0.f, q1 = 0.f;
#pragma unroll
                for (int i = 0; i < 16; i++) {
                    const float d0 = v0[i] - mu0, d1 = v1[i] - mu1;
                    q0 += d0 * d0; q1 += d1 * d1;
                }
                q0 += __shfl_xor_sync(0xffffffffu, q0, 1);
                q0 += __shfl_xor_sync(0xffffffffu, q0, 2);
                q1 += __shfl_xor_sync(0xffffffffu, q1, 1);
                q1 += __shfl_xor_sync(0xffffffffu, q1, 2);
                const float r0 = rsqrtf(q0 * (1.f / 64.f) + 1e-5f);
                const float r1 = rsqrtf(q1 * (1.f / 64.f) + 1e-5f);
#pragma unroll
                for (int nt = 0; nt < 8; nt++) {
                    const int gn = bx * BN + wn * 64 + nt * 8 + lc * 2;
                    const int d = nt * 8 + lc * 2;
                    const float w0 = lw[d], w1 = lw[d + 1];
                    const float c0 = lb[d], c1 = lb[d + 1];
                    *(uint32_t*)((__half*)C + (size_t)gm * ldc + gn) =
                        pack_h2f((v0[2*nt] - mu0) * r0 * w0 + c0,
                                 (v0[2*nt+1] - mu0) * r0 * w1 + c1);
                    *(uint32_t*)((__half*)C + (size_t)(gm + 8) * ldc + gn) =
                        pack_h2f((v1[2*nt] - mu1) * r1 * w0 + c0,
                                 (v1[2*nt+1] - mu1) * r1 * w1 + c1);
                }
            }
        }
        return;
    }

#pragma unroll
    for (int mt = 0; mt < 2; mt++) {
        const int gm = by * BM + wm * 32 + mt * 16 + lr;
#pragma unroll
        for (int nt = 0; nt < 8; nt++) {
            const int gn = bx * BN + wn * 64 + nt * 8 + lc * 2;
            const float b0 = bias[gn], b1 = bias[gn + 1];
            float v00 = acc[mt][nt][0] + b0, v01 = acc[mt][nt][1] + b1;
            float v10 = acc[mt][nt][2] + b0, v11 = acc[mt][nt][3] + b1;
            if (EPI == 2) {
                __half* Ch = (__half*)C;
                Ch[(size_t)gm * ldc + (gn >> 1)]       = __float2half(v00 * siluf(v01));
                Ch[(size_t)(gm + 8) * ldc + (gn >> 1)] = __float2half(v10 * siluf(v11));
                continue;
            }
            if (RESID) {
                float2 r0 = *(const float2*)(R + (size_t)gm * ldr + gn);
                float2 r1 = *(const float2*)(R + (size_t)(gm + 8) * ldr + gn);
                v00 += r0.x; v01 += r0.y;
                v10 += r1.x; v11 += r1.y;
            }
            if (EPI == 1) {
                v00 = siluf(v00); v01 = siluf(v01);
                v10 = siluf(v10); v11 = siluf(v11);
            }
            if (sizeof(OutT) == 2) {
                *(uint32_t*)((__half*)C + (size_t)gm * ldc + gn) = pack_h2f(v00, v01);
                *(uint32_t*)((__half*)C + (size_t)(gm + 8) * ldc + gn) = pack_h2f(v10, v11);
            } else {
                *(float2*)((float*)C + (size_t)gm * ldc + gn) = make_float2(v00, v01);
                *(float2*)((float*)C + (size_t)(gm + 8) * ldc + gn) = make_float2(v10, v11);
            }
        }
    }
}

// ---------------- block reduce helper ----------------
__device__ __forceinline__ float block_reduce_sum(float v)
{
    __shared__ float shr[32];
    const int lane = threadIdx.x & 31, wid = threadIdx.x >> 5;
#pragma unroll
    for (int o = 16; o > 0; o >>= 1) v += __shfl_xor_sync(0xffffffffu, v, o);
    __syncthreads();
    if (lane == 0) shr[wid] = v;
    __syncthreads();
    const int nw = blockDim.x >> 5;
    float r = (threadIdx.x < nw) ? shr[threadIdx.x] : 0.f;
    if (wid == 0) {
#pragma unroll
        for (int o = 16; o > 0; o >>= 1) r += __shfl_xor_sync(0xffffffffu, r, o);
        if (lane == 0) shr[0] = r;
    }
    __syncthreads();
    return shr[0];
}

// ---------------- LN(x)*(1+scale)+shift -> half ----------------
__global__ void __launch_bounds__(256) k_lnmod(
    const float* __restrict__ x, const float* __restrict__ lnw,
    const float* __restrict__ lnb, const __half* __restrict__ se,
    __half* __restrict__ xn)
{
    const int r = blockIdx.x, tid = threadIdx.x;
    const float4 v = ((const float4*)(x + (size_t)r * C_DIM))[tid];
    float s = v.x + v.y + v.z + v.w;
    s = block_reduce_sum(s);
    const float mu = s * (1.f / 1024.f);
    const float dx0 = v.x - mu, dx1 = v.y - mu, dx2 = v.z - mu, dx3 = v.w - mu;
    float q = dx0 * dx0 + dx1 * dx1 + dx2 * dx2 + dx3 * dx3;
    q = block_reduce_sum(q);
    const float rstd = rsqrtf(q * (1.f / 1024.f) + 1e-5f);
    const float4 w = ((const float4*)lnw)[tid];
    const float4 bb = ((const float4*)lnb)[tid];
    const __half2* sep = (const __half2*)(se + (size_t)r * SE_N);
    const float2 sc01 = __half22float2(sep[tid * 2]);
    const float2 sc23 = __half22float2(sep[tid * 2 + 1]);
    const float2 sf01 = __half22float2(sep[512 + tid * 2]);
    const float2 sf23 = __half22float2(sep[512 + tid * 2 + 1]);
    const float o0 = (dx0 * rstd * w.x + bb.x) * (1.f + sc01.x) + sf01.x;
    const float o1 = (dx1 * rstd * w.y + bb.y) * (1.f + sc01.y) + sf01.y;
    const float o2 = (dx2 * rstd * w.z + bb.z) * (1.f + sc23.x) + sf23.x;
    const float o3 = (dx3 * rstd * w.w + bb.w) * (1.f + sc23.y) + sf23.y;
    ((uint2*)(xn + (size_t)r * C_DIM))[tid] =
        make_uint2(pack_h2f(o0, o1), pack_h2f(o2, o3));
}

// ---------------- fp16 mma.sync flash attention ----------------
#define QH 72
#define KH 72
#define VH 72
#define ATT_SMEM ((128*QH + 2*64*KH + 2*64*VH) * (int)sizeof(__half))

__global__ void __launch_bounds__(256) k_attn_h(
    const __half* __restrict__ qkv, __half* __restrict__ o)
{
    extern __shared__ __half shh[];
    __half* Qs = shh;
    __half* Ks = Qs + 128 * QH;
    __half* Vs = Ks + 2 * 64 * KH;

    const int qt = blockIdx.x, bh = blockIdx.y;
    const int b = bh >> 4, h = bh & 15;
    const int tid = threadIdx.x;
    const int warp = tid >> 5, lane = tid & 31;
    const int lr = lane >> 2, lc = lane & 3;

    const __half* qbase = qkv + (size_t)(b * 2048 + qt * 128) * QKV_N + h * D_DIM;
    const __half2 scl = __float2half2_rn(0.125f);
    for (int it = tid; it < 4096; it += 256) {
        const int r = it >> 5, c = (it & 31) * 2;
        __half2 v = *(const __half2*)(qbase + (size_t)r * QKV_N + c);
        *(__half2*)(Qs + r * QH + c) = __hmul2(v, scl);
    }

    auto load_kv = [&](int s, int kt) {
        const __half* kb = qkv + (size_t)(b * 2048 + kt * 64) * QKV_N + C_DIM + h * D_DIM;
        const __half* vb = kb + C_DIM;
        __half* Kd = Ks + s * 64 * KH;
        __half* Vd = Vs + s * 64 * VH;
        for (int it = tid; it < 512; it += 256) {
            const int r = it >> 3, c = (it & 7) * 8;
            uint32_t dk = (uint32_t)__cvta_generic_to_shared(Kd + r * KH + c);
            asm volatile("cp.async.cg.shared.global [%0], [%1], 16;\n"
                         :: "r"(dk), "l"(kb + (size_t)r * QKV_N + c));
            uint32_t dv = (uint32_t)__cvta_generic_to_shared(Vd + r * VH + c);
            asm volatile("cp.async.cg.shared.global [%0], [%1], 16;\n"
                         :: "r"(dv), "l"(vb + (size_t)r * QKV_N + c));
        }
        asm volatile("cp.async.commit_group;\n");
    };

    load_kv(0, 0);
    asm volatile("cp.async.wait_group 0;\n");
    __syncthreads();

    uint32_t qa[4][4];
#pragma unroll
    for (int kf = 0; kf < 4; kf++) {
        uint32_t ad = (uint32_t)__cvta_generic_to_shared(
            Qs + (warp * 16 + (lane & 15)) * QH + kf * 16 + (lane >> 4) * 8);
        LDSM_X4(qa[kf][0], qa[kf][1], qa[kf][2], qa[kf][3], ad);
    }

    float m0 = -1e30f, m1 = -1e30f, l0 = 0.f, l1 = 0.f;
    float oa[8][4];
#pragma unroll
    for (int dt = 0; dt < 8; dt++)
#pragma unroll
        for (int i = 0; i < 4; i++) oa[dt][i] = 0.f;

    for (int kt = 0; kt < 32; kt++) {
        const int s = kt & 1;
        if (kt + 1 < 32) load_kv(1 - s, kt + 1);

        const __half* Kd = Ks + s * 64 * KH;
        const __half* Vd = Vs + s * 64 * VH;

        float acc[8][4];
#pragma unroll
        for (int nt = 0; nt < 8; nt++)
#pragma unroll
            for (int i = 0; i < 4; i++) acc[nt][i] = 0.f;

        const int g = lane >> 3;
#pragma unroll
        for (int kf = 0; kf < 4; kf++) {
#pragma unroll
            for (int nb = 0; nb < 4; nb++) {
                uint32_t b0, b1, b2, b3;
                uint32_t bd = (uint32_t)__cvta_generic_to_shared(
                    Kd + (nb * 16 + (g >> 1) * 8 + (lane & 7)) * KH +
                    kf * 16 + (g & 1) * 8);
                LDSM_X4(b0, b1, b2, b3, bd);
                MMA_F16(acc[2*nb],   qa[kf][0], qa[kf][1], qa[kf][2], qa[kf][3], b0, b1);
                MMA_F16(acc[2*nb+1], qa[kf][0], qa[kf][1], qa[kf][2], qa[kf][3], b2, b3);
            }
        }

        float mx0 = -1e30f, mx1 = -1e30f;
#pragma unroll
        for (int nt = 0; nt < 8; nt++) {
            mx0 = fmaxf(mx0, fmaxf(acc[nt][0], acc[nt][1]));
            mx1 = fmaxf(mx1, fmaxf(acc[nt][2], acc[nt][3]));
        }
        mx0 = fmaxf(mx0, __shfl_xor_sync(0xffffffffu, mx0, 1));
        mx0 = fmaxf(mx0, __shfl_xor_sync(0xffffffffu, mx0, 2));
        mx1 = fmaxf(mx1, __shfl_xor_sync(0xffffffffu, mx1, 1));
        mx1 = fmaxf(mx1, __shfl_xor_sync(0xffffffffu, mx1, 2));
        const float mn0 = fmaxf(m0, mx0), mn1 = fmaxf(m1, mx1);
        const float al0 = __expf(m0 - mn0), al1 = __expf(m1 - mn1);
        m0 = mn0; m1 = mn1;
        float rs0 = 0.f, rs1 = 0.f;
#pragma unroll
        for (int nt = 0; nt < 8; nt++) {
            acc[nt][0] = __expf(acc[nt][0] - mn0);
            acc[nt][1] = __expf(acc[nt][1] - mn0);
            acc[nt][2] = __expf(acc[nt][2] - mn1);
            acc[nt][3] = __expf(acc[nt][3] - mn1);
            rs0 += acc[nt][0] + acc[nt][1];
            rs1 += acc[nt][2] + acc[nt][3];
        }
        rs0 += __shfl_xor_sync(0xffffffffu, rs0, 1);
        rs0 += __shfl_xor_sync(0xffffffffu, rs0, 2);
        rs1 += __shfl_xor_sync(0xffffffffu, rs1, 1);
        rs1 += __shfl_xor_sync(0xffffffffu, rs1, 2);
        l0 = l0 * al0 + rs0;
        l1 = l1 * al1 + rs1;
#pragma unroll
        for (int dt = 0; dt < 8; dt++) {
            oa[dt][0] *= al0; oa[dt][1] *= al0;
            oa[dt][2] *= al1; oa[dt][3] *= al1;
        }

#pragma unroll
        for (int c = 0; c < 4; c++) {
            const uint32_t a0 = pack_h2f(acc[2*c][0],   acc[2*c][1]);
            const uint32_t a1 = pack_h2f(acc[2*c][2],   acc[2*c][3]);
            const uint32_t a2 = pack_h2f(acc[2*c+1][0], acc[2*c+1][1]);
            const uint32_t a3 = pack_h2f(acc[2*c+1][2], acc[2*c+1][3]);
#pragma unroll
            for (int nb = 0; nb < 4; nb++) {
                uint32_t v0, v1, v2, v3;
                uint32_t vd = (uint32_t)__cvta_generic_to_shared(
                    Vd + (c * 16 + (lane & 15)) * VH + nb * 16 + (lane >> 4) * 8);
                LDSM_X4T(v0, v1, v2, v3, vd);
                MMA_F16(oa[2*nb],   a0, a1, a2, a3, v0, v1);
                MMA_F16(oa[2*nb+1], a0, a1, a2, a3, v2, v3);
            }
        }

        if (kt + 1 < 32) {
            asm volatile("cp.async.wait_group 0;\n");
            __syncthreads();
        }
    }

    const float i0 = 1.f / l0, i1 = 1.f / l1;
    __half* ob = o + (size_t)(b * 2048 + qt * 128 + warp * 16 + lr) * OMLP_N + h * D_DIM;
#pragma unroll
    for (int dt = 0; dt < 8; dt++) {
        *(uint32_t*)(ob + dt * 8 + 2 * lc) =
            pack_h2f(oa[dt][0] * i0, oa[dt][1] * i0);
        *(uint32_t*)(ob + 8 * OMLP_N + dt * 8 + 2 * lc) =
            pack_h2f(oa[dt][2] * i1, oa[dt][3] * i1);
    }
}

// ---------------- gate = tanh(x @ W_g + b_g) ----------------
__global__ void __launch_bounds__(256) k_gate(
    const float* __restrict__ x, const float* __restrict__ Wg,
    const float* __restrict__ bg, float* __restrict__ gate)
{
    __shared__ float xs[1024];
    __shared__ float part[16][17];
    const int r = blockIdx.x, tid = threadIdx.x;
    *(float4*)&xs[tid * 4] = ((const float4*)(x + (size_t)r * C_DIM))[tid];
    __syncthreads();
    const int h = tid & 15, seg = tid >> 4;
    float s = 0.f;
#pragma unroll 8
    for (int c = seg * 64; c < seg * 64 + 64; c++) s += xs[c] * Wg[c * 16 + h];
    part[h][seg] = s;
    __syncthreads();
    if (tid < 16) {
        float t = bg[tid];
#pragma unroll
        for (int sg = 0; sg < 16; sg++) t += part[tid][sg];
        gate[(size_t)r * 16 + tid] = tanhf(t);
    }
}

// ---------------- rms[b,h] over (n,d) of f (half) ----------------
__global__ void __launch_bounds__(256) k_rms(const __half* __restrict__ f, float* __restrict__ rms)
{
    const int b = blockIdx.x >> 4, h = blockIdx.x & 15;
    float s = 0.f;
    for (int n = threadIdx.x; n < 2048; n += 256) {
        const __half2* fp = (const __half2*)(f + (size_t)(b * 2048 + n) * C_DIM + h * D_DIM);
#pragma unroll
        for (int d2 = 0; d2 < 32; d2++) {
            const float2 v = __half22float2(fp[d2]);
            s += v.x * v.x + v.y * v.y;
        }
    }
    s = block_reduce_sum(s);
    if (threadIdx.x == 0)
        rms[blockIdx.x] = fmaxf(sqrtf(s * (1.f / 131072.f)), 1e-6f);
}

// ---------------- o = half(o + gate * f / rms), o inside omlp --------------
__global__ void __launch_bounds__(256) k_combine(
    __half* __restrict__ o, const __half* __restrict__ f,
    const float* __restrict__ gate, const float* __restrict__ rms)
{
    const int r = blockIdx.x, tid = threadIdx.x;
    const int h = tid >> 4;
    const float g = gate[(size_t)r * 16 + h] / rms[(r >> 11) * 16 + h];
    __half2* op = (__half2*)(o + (size_t)r * OMLP_N) + tid * 2;
    const __half2* fp = (const __half2*)(f + (size_t)r * C_DIM) + tid * 2;
    const float2 f01 = __half22float2(fp[0]);
    const float2 f23 = __half22float2(fp[1]);
    float2 a = __half22float2(op[0]);
    float2 bq = __half22float2(op[1]);
    a.x += g * f01.x; a.y += g * f01.y;
    bq.x += g * f23.x; bq.y += g * f23.y;
    op[0] = __floats2half2_rn(a.x, a.y);
    op[1] = __floats2half2_rn(bq.x, bq.y);
}

// ---------------- launch ----------------
extern "C" void kernel_launch(void* const* d_in, const int* in_sizes, int n_in,
                              void* d_out, int out_size)
{
    const float* x     = (const float*)d_in[0];
    const float* emb   = (const float*)d_in[1];
    const float* W_emb = (const float*)d_in[2];
    const float* b_emb = (const float*)d_in[3];
    const float* ln_w  = (const float*)d_in[4];
    const float* ln_b  = (const float*)d_in[5];
    const float* W_f   = (const float*)d_in[6];
    const float* b_f   = (const float*)d_in[7];
    const float* qn_w  = (const float*)d_in[8];
    const float* qn_b  = (const float*)d_in[9];
    const float* kn_w  = (const float*)d_in[10];
    const float* kn_b  = (const float*)d_in[11];
    const float* W_ao  = (const float*)d_in[12];
    const float* b_ao  = (const float*)d_in[13];
    const float* W_mo  = (const float*)d_in[14];
    const float* b_mo  = (const float*)d_in[15];
    const float* Wm_in = (const float*)d_in[16];
    const float* bm_in = (const float*)d_in[17];
    const float* Wm_out= (const float*)d_in[18];
    const float* bm_out= (const float*)d_in[19];
    const float* W_g   = (const float*)d_in[20];
    const float* b_g   = (const float*)d_in[21];
    float* out = (float*)d_out;

    float *gate, *rms, *bmin, *bcomb;
    __half *se, *xn, *qkv, *omlp, *h2, *f;
    __half *embt, *Wembh, *Wfh, *Wminh, *Wmoh, *Wcomb;
    cudaGetSymbolAddress((void**)&se,    g_se);
    cudaGetSymbolAddress((void**)&xn,    g_xn);
    cudaGetSymbolAddress((void**)&qkv,   g_qkv);
    cudaGetSymbolAddress((void**)&omlp,  g_omlp);
    cudaGetSymbolAddress((void**)&h2,    g_h2);
    cudaGetSymbolAddress((void**)&f,     g_f);
    cudaGetSymbolAddress((void**)&gate,  g_gate);
    cudaGetSymbolAddress((void**)&rms,   g_rms);
    cudaGetSymbolAddress((void**)&embt,  g_embt);
    cudaGetSymbolAddress((void**)&Wembh, g_Wembh);
    cudaGetSymbolAddress((void**)&Wfh,   g_Wfh);
    cudaGetSymbolAddress((void**)&Wminh, g_Wminh);
    cudaGetSymbolAddress((void**)&bmin,  g_bmin);
    cudaGetSymbolAddress((void**)&Wmoh,  g_Wmoh);
    cudaGetSymbolAddress((void**)&Wcomb, g_Wcomb);
    cudaGetSymbolAddress((void**)&bcomb, g_bcomb);

    cudaFuncSetAttribute(tgemm_h<__half, false, 0>, cudaFuncAttributeMaxDynamicSharedMemorySize, GSMEM);
    cudaFuncSetAttribute(tgemm_h<__half, false, 2>, cudaFuncAttributeMaxDynamicSharedMemorySize, GSMEM);
    cudaFuncSetAttribute(tgemm_h<__half, false, 3>, cudaFuncAttributeMaxDynamicSharedMemorySize, GSMEM);
    cudaFuncSetAttribute(tgemm_h<float, true, 0>,   cudaFuncAttributeMaxDynamicSharedMemorySize, GSMEM);
    cudaFuncSetAttribute(k_attn_h, cudaFuncAttributeMaxDynamicSharedMemorySize, ATT_SMEM);

    const int MB = T_ROWS / 128;  // 64
    dim3 blk(256);

    // ---- merged operand prep ----
    CvtTasks tasks;
    int bs = 0;
    tasks.t[0] = { emb,    embt,  T_ROWS,  C_DIM,   C_DIM,   bs }; bs += T_ROWS  * (C_DIM   / 1024);
    tasks.t[1] = { W_emb,  Wembh, C_DIM,   SE_N,    SE_N,    bs }; bs += C_DIM   * (SE_N    / 1024);
    tasks.t[2] = { W_f,    Wfh,   C_DIM,   FUSED_N, FUSED_N, bs }; bs += C_DIM   * (FUSED_N / 1024);
    tasks.t[3] = { Wm_out, Wmoh,  INNER,   C_DIM,   C_DIM,   bs }; bs += INNER_P * (C_DIM   / 1024);
    tasks.t[4] = { W_ao,   Wcomb, C_DIM,   C_DIM,   C_DIM,   bs }; bs += C_DIM   * (C_DIM   / 1024);
    tasks.t[5] = { W_mo,   Wcomb + (size_t)C_DIM * C_DIM,
                           MLP_DIM, C_DIM, C_DIM,   bs }; bs += MLP_DIM * (C_DIM / 1024);
    k_cvt_all<<<dim3(bs), blk>>>(tasks);
    k_cvt_gluW4<<<dim3((VG_P / 4 + 255) / 256, C_DIM), blk>>>(Wm_in, Wminh);
    k_misc<<<dim3(26), blk>>>(bm_in, bmin, b_ao, b_mo, bcomb);

    // se = emb @ W_emb + b_emb  (half out)
    tgemm_h<__half, false, 0><<<dim3(SE_N / 128, MB), blk, GSMEM>>>(
        embt, C_DIM, Wembh, SE_N, b_emb, nullptr, 0, se, SE_N, C_DIM, nullptr, 0,
        nullptr, nullptr, nullptr, nullptr);

    // xn = LN(x)*(1+scale)+shift
    k_lnmod<<<T_ROWS, blk>>>(x, ln_w, ln_b, se, xn);

    // fused: q,k (LN'd) + v -> qkv ; mlps (silu) -> omlp cols [1024:5120)
    tgemm_h<__half, false, 3><<<dim3(FUSED_N / 128, MB), blk, GSMEM>>>(
        xn, C_DIM, Wfh, FUSED_N, b_f, nullptr, 0, qkv, QKV_N, C_DIM,
        omlp + C_DIM, OMLP_N, qn_w, qn_b, kn_w, kn_b);

    // flash attention -> omlp cols [0:1024)
    k_attn_h<<<dim3(16, 64), blk, ATT_SMEM>>>(qkv, omlp);

    // h2 = silu(g)*vv fused in GEMM epilogue (paired weights)
    tgemm_h<__half, false, 2><<<dim3(VG_P / 128, MB), blk, GSMEM>>>(
        qkv, QKV_N, Wminh, VG_P, bmin, nullptr, 0, h2, INNER_P, C_DIM, nullptr, 0,
        nullptr, nullptr, nullptr, nullptr);

    // f = h2 @ Wm_out + bm_out  (half out)
    tgemm_h<__half, false, 0><<<dim3(C_DIM / 128, MB), blk, GSMEM>>>(
        h2, INNER_P, Wmoh, C_DIM, bm_out, nullptr, 0, f, C_DIM, INNER_P, nullptr, 0,
        nullptr, nullptr, nullptr, nullptr);

    // gate, rms, combine (updates o-region of omlp in place)
    k_gate<<<T_ROWS, blk>>>(x, W_g, b_g, gate);
    k_rms<<<4 * H_DIM, blk>>>(f, rms);
    k_combine<<<T_ROWS, blk>>>(omlp, f, gate, rms);

    // out = x + [o|mlps] @ [W_ao;W_mo] + (b_ao+b_mo)   — fused K=5120
    tgemm_h<float, true, 0><<<dim3(C_DIM / 128, MB), blk, GSMEM>>>(
        omlp, OMLP_N, Wcomb, C_DIM, bcomb, x, C_DIM, out, C_DIM, OMLP_N, nullptr, 0,
        nullptr, nullptr, nullptr, nullptr);
}

// round 17
// speedup vs baseline: 1.1087x; 1.0038x over previous
#include <cuda_runtime.h>
#include <cuda_fp16.h>
#include <math.h>
#include <stdint.h>

// Problem constants
#define T_ROWS   8192            // B*N
#define C_DIM    1024
#define H_DIM    16
#define D_DIM    64
#define QKV_N    3072
#define SE_N     2048
#define MLP_DIM  4096
#define FUSED_N  7168
#define INNER    2730
#define INNER_P  2816            // padded (mult of 128)
#define VG_P     5632            // 2*INNER_P (paired layout)
#define OMLP_N   5120            // 1024 (o) + 4096 (mlps)

// ---------------- scratch (static device allocations) ----------------
__device__ __half g_se   [T_ROWS * SE_N];
__device__ __half g_xn   [T_ROWS * C_DIM];
__device__ __half g_qkv  [(size_t)T_ROWS * QKV_N];
__device__ __half g_omlp [(size_t)T_ROWS * OMLP_N];   // [o | mlps]
__device__ __half g_h2   [(size_t)T_ROWS * INNER_P];
__device__ __half g_f    [T_ROWS * C_DIM];
__device__ float  g_gate [T_ROWS * H_DIM];
__device__ float  g_rms  [4 * H_DIM];
// half-converted operands ([K][N] row-major)
__device__ __half g_embt [T_ROWS * C_DIM];
__device__ __half g_Wembh[C_DIM * SE_N];
__device__ __half g_Wfh  [(size_t)C_DIM * FUSED_N];
__device__ __half g_Wminh[(size_t)C_DIM * VG_P];      // paired [vv|g] cols
__device__ float  g_bmin [VG_P];
__device__ __half g_Wmoh [INNER_P * C_DIM];
__device__ __half g_Wcomb[OMLP_N * C_DIM];            // [W_ao ; W_mo]
__device__ float  g_bcomb[C_DIM];

__device__ __forceinline__ uint32_t pack_h2f(float lo, float hi)
{
    uint32_t u;
    asm("cvt.rn.f16x2.f32 %0, %1, %2;" : "=r"(u) : "f"(hi), "f"(lo));
    return u;
}
__device__ __forceinline__ float siluf(float g) { return g / (1.f + __expf(-g)); }

// ---------------- merged convert megakernel ----------------
struct CvtTask { const float* src; __half* dst; int rows_in, cols_in, cols_out, blk_start; };
struct CvtTasks { CvtTask t[6]; };

__global__ void __launch_bounds__(256) k_cvt_all(CvtTasks tasks)
{
    const int bid = blockIdx.x;
    int i = 0;
#pragma unroll
    for (int j = 1; j < 6; j++)
        if (bid >= tasks.t[j].blk_start) i = j;
    const CvtTask tk = tasks.t[i];
    const int rel = bid - tk.blk_start;
    const int cpr = tk.cols_out >> 10;          // 1024-col chunks per row
    const int r = rel / cpr, cc = rel - r * cpr;
    const int c = cc * 1024 + threadIdx.x * 4;
    float4 v = make_float4(0.f, 0.f, 0.f, 0.f);
    if (r < tk.rows_in && c < tk.cols_in)
        v = *(const float4*)(tk.src + (size_t)r * tk.cols_in + c);
    *(uint2*)(tk.dst + (size_t)r * tk.cols_out + c) =
        make_uint2(pack_h2f(v.x, v.y), pack_h2f(v.z, v.w));
}

__global__ void __launch_bounds__(256) k_cvt_gluW4(
    const float* __restrict__ in, __half* __restrict__ out)
{
    const int c4 = (blockIdx.x * 256 + threadIdx.x) * 4;
    const int r = blockIdx.y;
    if (c4 >= VG_P) return;
    const int p0 = c4 >> 1;                 // even
    float2 vv = make_float2(0.f, 0.f), gg = make_float2(0.f, 0.f);
    if (p0 + 1 < INNER) {
        vv = *(const float2*)(in + (size_t)r * (2 * INNER) + p0);
        gg = *(const float2*)(in + (size_t)r * (2 * INNER) + INNER + p0);
    }
    *(uint2*)(out + (size_t)r * VG_P + c4) =
        make_uint2(pack_h2f(vv.x, gg.x), pack_h2f(vv.y, gg.y));
}

// blocks [0,22): pad_glub; blocks [22,26): addb
__global__ void __launch_bounds__(256) k_misc(
    const float* __restrict__ bm_in, float* __restrict__ bmin,
    const float* __restrict__ b_ao, const float* __restrict__ b_mo,
    float* __restrict__ bcomb)
{
    const int bid = blockIdx.x;
    if (bid < 22) {
        const int c = bid * 256 + threadIdx.x;
        if (c >= VG_P) return;
        const int pair = c >> 1, isg = c & 1;
        bmin[c] = (pair < INNER) ? bm_in[isg ? INNER + pair : pair] : 0.f;
    } else {
        const int c = (bid - 22) * 256 + threadIdx.x;
        if (c < C_DIM) bcomb[c] = b_ao[c] + b_mo[c];
    }
}

// ---------------- fp16 GEMM, 128x128x64, 256 threads, 3-stage cp.async ----
// 105 KB smem -> 2 CTAs/SM; fragment-level 2-deep software pipeline
#define BM 128
#define BN 128
#define BK 64
#define NSTG 3
#define AH 72     // BK+8 halves
#define BH 136    // BN+8 halves
#define GSMEM ((NSTG*BM*AH + NSTG*BK*BH) * (int)sizeof(__half))

#define MMA_F16(D, A0,A1,A2,A3, B0,B1)                                        \
    asm volatile(                                                             \
        "mma.sync.aligned.m16n8k16.row.col.f32.f16.f16.f32 "                  \
        "{%0,%1,%2,%3}, {%4,%5,%6,%7}, {%8,%9}, {%0,%1,%2,%3};\n"            \
        : "+f"((D)[0]), "+f"((D)[1]), "+f"((D)[2]), "+f"((D)[3])              \
        : "r"(A0), "r"(A1), "r"(A2), "r"(A3), "r"(B0), "r"(B1))

#define LDSM_X4(R0,R1,R2,R3, ADDR)                                            \
    asm volatile("ldmatrix.sync.aligned.m8n8.x4.shared.b16 "                  \
                 "{%0,%1,%2,%3}, [%4];"                                       \
                 : "=r"(R0), "=r"(R1), "=r"(R2), "=r"(R3) : "r"(ADDR))

#define LDSM_X4T(R0,R1,R2,R3, ADDR)                                           \
    asm volatile("ldmatrix.sync.aligned.m8n8.x4.trans.shared.b16 "            \
                 "{%0,%1,%2,%3}, [%4];"                                       \
                 : "=r"(R0), "=r"(R1), "=r"(R2), "=r"(R3) : "r"(ADDR))

// EPI: 0 none, 1 silu (half), 2 GLU pair -> half at gn/2,
//      3 fused-QKV+MLP: bx<8 qLN, bx<16 kLN, bx<24 plain v (all -> C),
//                       bx>=24 silu -> C2 at gn-QKV_N
template<typename OutT, bool RESID, int EPI>
__global__ void __launch_bounds__(256, 2) tgemm_h(
    const __half* __restrict__ A, int lda,
    const __half* __restrict__ B, int ldb,
    const float* __restrict__ bias,
    const float* __restrict__ R, int ldr,
    OutT* __restrict__ C, int ldc,
    int K,
    __half* __restrict__ C2, int ldc2,
    const float* __restrict__ qw, const float* __restrict__ qb,
    const float* __restrict__ kw, const float* __restrict__ kb)
{
    extern __shared__ __half sh[];
    __half* As = sh;                       // [NSTG][BM][AH]
    __half* Bs = sh + NSTG * BM * AH;      // [NSTG][BK][BH]

    const int tid  = threadIdx.x;
    const int warp = tid >> 5, lane = tid & 31;
    const int wm = warp & 3, wn = warp >> 2;     // 4 x 2 warps -> 32x64 tiles
    const int lr = lane >> 2, lc = lane & 3;
    const int bx = blockIdx.x, by = blockIdx.y;

    auto load_tile = [&](int stg, int k0) {
        __half* Asd = As + stg * BM * AH;
        __half* Bsd = Bs + stg * BK * BH;
#pragma unroll
        for (int i = 0; i < 4; i++) {               // 1024 A-chunks of 8 halves
            const int c = tid + i * 256;
            const int r = c >> 3, col = (c & 7) * 8;
            uint32_t d0 = (uint32_t)__cvta_generic_to_shared(Asd + r * AH + col);
            const __half* src = A + (size_t)(by * BM + r) * lda + k0 + col;
            asm volatile("cp.async.cg.shared.global [%0], [%1], 16;\n"
                         :: "r"(d0), "l"(src));
        }
#pragma unroll
        for (int i = 0; i < 4; i++) {               // 1024 B-chunks of 8 halves
            const int c = tid + i * 256;
            const int r = c >> 4, col = (c & 15) * 8;
            uint32_t d1 = (uint32_t)__cvta_generic_to_shared(Bsd + r * BH + col);
            const __half* src = B + (size_t)(k0 + r) * ldb + bx * BN + col;
            asm volatile("cp.async.cg.shared.global [%0], [%1], 16;\n"
                         :: "r"(d1), "l"(src));
        }
        asm volatile("cp.async.commit_group;\n");
    };

    float acc[2][8][4];
#pragma unroll
    for (int mt = 0; mt < 2; mt++)
#pragma unroll
        for (int nt = 0; nt < 8; nt++)
#pragma unroll
            for (int i = 0; i < 4; i++) acc[mt][nt][i] = 0.f;

    const int T = K / BK;
    load_tile(0, 0);
    if (T > 1) load_tile(1, BK);
    asm volatile("cp.async.wait_group 1;\n");
    __syncthreads();

    // double-buffered fragment registers
    uint32_t af[2][2][4];
    uint32_t bf[2][8][2];

    for (int kt = 0; kt < T; kt++) {
        const int stg = kt % NSTG;
        if (kt + 2 < T) load_tile((kt + 2) % NSTG, (kt + 2) * BK);

        const __half* Asd = As + stg * BM * AH;
        const __half* Bsd = Bs + stg * BK * BH;

        auto ldfrag = [&](int buf, int kf) {
#pragma unroll
            for (int mt = 0; mt < 2; mt++) {
                uint32_t ad = (uint32_t)__cvta_generic_to_shared(
                    Asd + (wm * 32 + mt * 16 + (lane & 15)) * AH +
                    kf * 16 + (lane >> 4) * 8);
                LDSM_X4(af[buf][mt][0], af[buf][mt][1],
                        af[buf][mt][2], af[buf][mt][3], ad);
            }
#pragma unroll
            for (int nb = 0; nb < 4; nb++) {
                uint32_t bd = (uint32_t)__cvta_generic_to_shared(
                    Bsd + (kf * 16 + (lane & 15)) * BH +
                    wn * 64 + nb * 16 + (lane >> 4) * 8);
                LDSM_X4T(bf[buf][2*nb][0], bf[buf][2*nb][1],
                         bf[buf][2*nb+1][0], bf[buf][2*nb+1][1], bd);
            }
        };

        ldfrag(0, 0);
#pragma unroll
        for (int kf = 0; kf < 4; kf++) {
            const int cur = kf & 1;
            if (kf < 3) ldfrag(cur ^ 1, kf + 1);
#pragma unroll
            for (int mt = 0; mt < 2; mt++)
#pragma unroll
                for (int nt = 0; nt < 8; nt++)
                    MMA_F16(acc[mt][nt],
                            af[cur][mt][0], af[cur][mt][1],
                            af[cur][mt][2], af[cur][mt][3],
                            bf[cur][nt][0], bf[cur][nt][1]);
        }
        if (kt + 1 < T) {
            if (kt + 3 <= T) asm volatile("cp.async.wait_group 1;\n");
            else             asm volatile("cp.async.wait_group 0;\n");
            __syncthreads();
        }
    }

    if (EPI == 3) {
        const int region = bx >> 3;        // 0 q, 1 k, 2 v, >=3 mlp
        if (region >= 2) {
#pragma unroll
            for (int mt = 0; mt < 2; mt++) {
                const int gm = by * BM + wm * 32 + mt * 16 + lr;
#pragma unroll
                for (int nt = 0; nt < 8; nt++) {
                    const int gn = bx * BN + wn * 64 + nt * 8 + lc * 2;
                    const float b0 = bias[gn], b1 = bias[gn + 1];
                    const float v00 = acc[mt][nt][0] + b0, v01 = acc[mt][nt][1] + b1;
                    const float v10 = acc[mt][nt][2] + b0, v11 = acc[mt][nt][3] + b1;
                    if (region == 2) {
                        *(uint32_t*)((__half*)C + (size_t)gm * ldc + gn) =
                            pack_h2f(v00, v01);
                        *(uint32_t*)((__half*)C + (size_t)(gm + 8) * ldc + gn) =
                            pack_h2f(v10, v11);
                    } else {
                        const int gn2 = gn - QKV_N;
                        *(uint32_t*)(C2 + (size_t)gm * ldc2 + gn2) =
                            pack_h2f(siluf(v00), siluf(v01));
                        *(uint32_t*)(C2 + (size_t)(gm + 8) * ldc2 + gn2) =
                            pack_h2f(siluf(v10), siluf(v11));
                    }
                }
            }
        } else {
            // per-head LayerNorm fused: warp's 64-col span == one head,
            // each row's 64 values live in one lane-quad (lr fixed, lc 0..3)
            const float* lw = (region == 0) ? qw : kw;
            const float* lb = (region == 0) ? qb : kb;
#pragma unroll
            for (int mt = 0; mt < 2; mt++) {
                const int gm = by * BM + wm * 32 + mt * 16 + lr;
                float v0[16], v1[16];
                float s0 = 0.f, s1 = 0.f;
#pragma unroll
                for (int nt = 0; nt < 8; nt++) {
                    const int gn = bx * BN + wn * 64 + nt * 8 + lc * 2;
                    const float b0 = bias[gn], b1 = bias[gn + 1];
                    v0[2*nt]   = acc[mt][nt][0] + b0;
                    v0[2*nt+1] = acc[mt][nt][1] + b1;
                    v1[2*nt]   = acc[mt][nt][2] + b0;
                    v1[2*nt+1] = acc[mt][nt][3] + b1;
                    s0 += v0[2*nt] + v0[2*nt+1];
                    s1 += v1[2*nt] + v1[2*nt+1];
                }
                s0 += __shfl_xor_sync(0xffffffffu, s0, 1);
                s0 += __shfl_xor_sync(0xffffffffu, s0, 2);
                s1 += __shfl_xor_sync(0xffffffffu, s1, 1);
                s1 += __shfl_xor_sync(0xffffffffu, s1, 2);
                const float mu0 = s0 * (1.f / 64.f), mu1 = s1 * (1.f / 64.f);
                float q0 = 0.f, q1 = 0.f;
#pragma unroll
                for (int i = 0; i < 16; i++) {
                    const float d0 = v0[i] - mu0, d1 = v1[i] - mu1;
                    q0 += d0 * d0; q1 += d1 * d1;
                }
                q0 += __shfl_xor_sync(0xffffffffu, q0, 1);
                q0 += __shfl_xor_sync(0xffffffffu, q0, 2);
                q1 += __shfl_xor_sync(0xffffffffu, q1, 1);
                q1 += __shfl_xor_sync(0xffffffffu, q1, 2);
                const float r0 = rsqrtf(q0 * (1.f / 64.f) + 1e-5f);
                const float r1 = rsqrtf(q1 * (1.f / 64.f) + 1e-5f);
#pragma unroll
                for (int nt = 0; nt < 8; nt++) {
                    const int gn = bx * BN + wn * 64 + nt * 8 + lc * 2;
                    const int d = nt * 8 + lc * 2;
                    const float w0 = lw[d], w1 = lw[d + 1];
                    const float c0 = lb[d], c1 = lb[d + 1];
                    *(uint32_t*)((__half*)C + (size_t)gm * ldc + gn) =
                        pack_h2f((v0[2*nt] - mu0) * r0 * w0 + c0,
                                 (v0[2*nt+1] - mu0) * r0 * w1 + c1);
                    *(uint32_t*)((__half*)C + (size_t)(gm + 8) * ldc + gn) =
                        pack_h2f((v1[2*nt] - mu1) * r1 * w0 + c0,
                                 (v1[2*nt+1] - mu1) * r1 * w1 + c1);
                }
            }
        }
        return;
    }

#pragma unroll
    for (int mt = 0; mt < 2; mt++) {
        const int gm = by * BM + wm * 32 + mt * 16 + lr;
#pragma unroll
        for (int nt = 0; nt < 8; nt++) {
            const int gn = bx * BN + wn * 64 + nt * 8 + lc * 2;
            const float b0 = bias[gn], b1 = bias[gn + 1];
            float v00 = acc[mt][nt][0] + b0, v01 = acc[mt][nt][1] + b1;
            float v10 = acc[mt][nt][2] + b0, v11 = acc[mt][nt][3] + b1;
            if (EPI == 2) {
                __half* Ch = (__half*)C;
                Ch[(size_t)gm * ldc + (gn >> 1)]       = __float2half(v00 * siluf(v01));
                Ch[(size_t)(gm + 8) * ldc + (gn >> 1)] = __float2half(v10 * siluf(v11));
                continue;
            }
            if (RESID) {
                float2 r0 = *(const float2*)(R + (size_t)gm * ldr + gn);
                float2 r1 = *(const float2*)(R + (size_t)(gm + 8) * ldr + gn);
                v00 += r0.x; v01 += r0.y;
                v10 += r1.x; v11 += r1.y;
            }
            if (EPI == 1) {
                v00 = siluf(v00); v01 = siluf(v01);
                v10 = siluf(v10); v11 = siluf(v11);
            }
            if (sizeof(OutT) == 2) {
                *(uint32_t*)((__half*)C + (size_t)gm * ldc + gn) = pack_h2f(v00, v01);
                *(uint32_t*)((__half*)C + (size_t)(gm + 8) * ldc + gn) = pack_h2f(v10, v11);
            } else {
                *(float2*)((float*)C + (size_t)gm * ldc + gn) = make_float2(v00, v01);
                *(float2*)((float*)C + (size_t)(gm + 8) * ldc + gn) = make_float2(v10, v11);
            }
        }
    }
}

// ---------------- block reduce helper ----------------
__device__ __forceinline__ float block_reduce_sum(float v)
{
    __shared__ float shr[32];
    const int lane = threadIdx.x & 31, wid = threadIdx.x >> 5;
#pragma unroll
    for (int o = 16; o > 0; o >>= 1) v += __shfl_xor_sync(0xffffffffu, v, o);
    __syncthreads();
    if (lane == 0) shr[wid] = v;
    __syncthreads();
    const int nw = blockDim.x >> 5;
    float r = (threadIdx.x < nw) ? shr[threadIdx.x] : 0.f;
    if (wid == 0) {
#pragma unroll
        for (int o = 16; o > 0; o >>= 1) r += __shfl_xor_sync(0xffffffffu, r, o);
        if (lane == 0) shr[0] = r;
    }
    __syncthreads();
    return shr[0];
}

// ---------------- LN(x)*(1+scale)+shift -> half ----------------
__global__ void __launch_bounds__(256) k_lnmod(
    const float* __restrict__ x, const float* __restrict__ lnw,
    const float* __restrict__ lnb, const __half* __restrict__ se,
    __half* __restrict__ xn)
{
    const int r = blockIdx.x, tid = threadIdx.x;
    const float4 v = ((const float4*)(x + (size_t)r * C_DIM))[tid];
    float s = v.x + v.y + v.z + v.w;
    s = block_reduce_sum(s);
    const float mu = s * (1.f / 1024.f);
    const float dx0 = v.x - mu, dx1 = v.y - mu, dx2 = v.z - mu, dx3 = v.w - mu;
    float q = dx0 * dx0 + dx1 * dx1 + dx2 * dx2 + dx3 * dx3;
    q = block_reduce_sum(q);
    const float rstd = rsqrtf(q * (1.f / 1024.f) + 1e-5f);
    const float4 w = ((const float4*)lnw)[tid];
    const float4 bb = ((const float4*)lnb)[tid];
    const __half2* sep = (const __half2*)(se + (size_t)r * SE_N);
    const float2 sc01 = __half22float2(sep[tid * 2]);
    const float2 sc23 = __half22float2(sep[tid * 2 + 1]);
    const float2 sf01 = __half22float2(sep[512 + tid * 2]);
    const float2 sf23 = __half22float2(sep[512 + tid * 2 + 1]);
    const float o0 = (dx0 * rstd * w.x + bb.x) * (1.f + sc01.x) + sf01.x;
    const float o1 = (dx1 * rstd * w.y + bb.y) * (1.f + sc01.y) + sf01.y;
    const float o2 = (dx2 * rstd * w.z + bb.z) * (1.f + sc23.x) + sf23.x;
    const float o3 = (dx3 * rstd * w.w + bb.w) * (1.f + sc23.y) + sf23.y;
    ((uint2*)(xn + (size_t)r * C_DIM))[tid] =
        make_uint2(pack_h2f(o0, o1), pack_h2f(o2, o3));
}

// ---------------- fp16 mma.sync flash attention ----------------
#define QH 72
#define KH 72
#define VH 72
#define ATT_SMEM ((128*QH + 2*64*KH + 2*64*VH) * (int)sizeof(__half))

__global__ void __launch_bounds__(256) k_attn_h(
    const __half* __restrict__ qkv, __half* __restrict__ o)
{
    extern __shared__ __half shh[];
    __half* Qs = shh;
    __half* Ks = Qs + 128 * QH;
    __half* Vs = Ks + 2 * 64 * KH;

    const int qt = blockIdx.x, bh = blockIdx.y;
    const int b = bh >> 4, h = bh & 15;
    const int tid = threadIdx.x;
    const int warp = tid >> 5, lane = tid & 31;
    const int lr = lane >> 2, lc = lane & 3;

    const __half* qbase = qkv + (size_t)(b * 2048 + qt * 128) * QKV_N + h * D_DIM;
    const __half2 scl = __float2half2_rn(0.125f);
    for (int it = tid; it < 4096; it += 256) {
        const int r = it >> 5, c = (it & 31) * 2;
        __half2 v = *(const __half2*)(qbase + (size_t)r * QKV_N + c);
        *(__half2*)(Qs + r * QH + c) = __hmul2(v, scl);
    }

    auto load_kv = [&](int s, int kt) {
        const __half* kb = qkv + (size_t)(b * 2048 + kt * 64) * QKV_N + C_DIM + h * D_DIM;
        const __half* vb = kb + C_DIM;
        __half* Kd = Ks + s * 64 * KH;
        __half* Vd = Vs + s * 64 * VH;
        for (int it = tid; it < 512; it += 256) {
            const int r = it >> 3, c = (it & 7) * 8;
            uint32_t dk = (uint32_t)__cvta_generic_to_shared(Kd + r * KH + c);
            asm volatile("cp.async.cg.shared.global [%0], [%1], 16;\n"
                         :: "r"(dk), "l"(kb + (size_t)r * QKV_N + c));
            uint32_t dv = (uint32_t)__cvta_generic_to_shared(Vd + r * VH + c);
            asm volatile("cp.async.cg.shared.global [%0], [%1], 16;\n"
                         :: "r"(dv), "l"(vb + (size_t)r * QKV_N + c));
        }
        asm volatile("cp.async.commit_group;\n");
    };

    load_kv(0, 0);
    asm volatile("cp.async.wait_group 0;\n");
    __syncthreads();

    uint32_t qa[4][4];
#pragma unroll
    for (int kf = 0; kf < 4; kf++) {
        uint32_t ad = (uint32_t)__cvta_generic_to_shared(
            Qs + (warp * 16 + (lane & 15)) * QH + kf * 16 + (lane >> 4) * 8);
        LDSM_X4(qa[kf][0], qa[kf][1], qa[kf][2], qa[kf][3], ad);
    }

    float m0 = -1e30f, m1 = -1e30f, l0 = 0.f, l1 = 0.f;
    float oa[8][4];
#pragma unroll
    for (int dt = 0; dt < 8; dt++)
#pragma unroll
        for (int i = 0; i < 4; i++) oa[dt][i] = 0.f;

    for (int kt = 0; kt < 32; kt++) {
        const int s = kt & 1;
        if (kt + 1 < 32) load_kv(1 - s, kt + 1);

        const __half* Kd = Ks + s * 64 * KH;
        const __half* Vd = Vs + s * 64 * VH;

        float acc[8][4];
#pragma unroll
        for (int nt = 0; nt < 8; nt++)
#pragma unroll
            for (int i = 0; i < 4; i++) acc[nt][i] = 0.f;

        const int g = lane >> 3;
#pragma unroll
        for (int kf = 0; kf < 4; kf++) {
#pragma unroll
            for (int nb = 0; nb < 4; nb++) {
                uint32_t b0, b1, b2, b3;
                uint32_t bd = (uint32_t)__cvta_generic_to_shared(
                    Kd + (nb * 16 + (g >> 1) * 8 + (lane & 7)) * KH +
                    kf * 16 + (g & 1) * 8);
                LDSM_X4(b0, b1, b2, b3, bd);
                MMA_F16(acc[2*nb],   qa[kf][0], qa[kf][1], qa[kf][2], qa[kf][3], b0, b1);
                MMA_F16(acc[2*nb+1], qa[kf][0], qa[kf][1], qa[kf][2], qa[kf][3], b2, b3);
            }
        }

        float mx0 = -1e30f, mx1 = -1e30f;
#pragma unroll
        for (int nt = 0; nt < 8; nt++) {
            mx0 = fmaxf(mx0, fmaxf(acc[nt][0], acc[nt][1]));
            mx1 = fmaxf(mx1, fmaxf(acc[nt][2], acc[nt][3]));
        }
        mx0 = fmaxf(mx0, __shfl_xor_sync(0xffffffffu, mx0, 1));
        mx0 = fmaxf(mx0, __shfl_xor_sync(0xffffffffu, mx0, 2));
        mx1 = fmaxf(mx1, __shfl_xor_sync(0xffffffffu, mx1, 1));
        mx1 = fmaxf(mx1, __shfl_xor_sync(0xffffffffu, mx1, 2));
        const float mn0 = fmaxf(m0, mx0), mn1 = fmaxf(m1, mx1);
        const float al0 = __expf(m0 - mn0), al1 = __expf(m1 - mn1);
        m0 = mn0; m1 = mn1;
        float rs0 = 0.f, rs1 = 0.f;
#pragma unroll
        for (int nt = 0; nt < 8; nt++) {
            acc[nt][0] = __expf(acc[nt][0] - mn0);
            acc[nt][1] = __expf(acc[nt][1] - mn0);
            acc[nt][2] = __expf(acc[nt][2] - mn1);
            acc[nt][3] = __expf(acc[nt][3] - mn1);
            rs0 += acc[nt][0] + acc[nt][1];
            rs1 += acc[nt][2] + acc[nt][3];
        }
        rs0 += __shfl_xor_sync(0xffffffffu, rs0, 1);
        rs0 += __shfl_xor_sync(0xffffffffu, rs0, 2);
        rs1 += __shfl_xor_sync(0xffffffffu, rs1, 1);
        rs1 += __shfl_xor_sync(0xffffffffu, rs1, 2);
        l0 = l0 * al0 + rs0;
        l1 = l1 * al1 + rs1;
#pragma unroll
        for (int dt = 0; dt < 8; dt++) {
            oa[dt][0] *= al0; oa[dt][1] *= al0;
            oa[dt][2] *= al1; oa[dt][3] *= al1;
        }

#pragma unroll
        for (int c = 0; c < 4; c++) {
            const uint32_t a0 = pack_h2f(acc[2*c][0],   acc[2*c][1]);
            const uint32_t a1 = pack_h2f(acc[2*c][2],   acc[2*c][3]);
            const uint32_t a2 = pack_h2f(acc[2*c+1][0], acc[2*c+1][1]);
            const uint32_t a3 = pack_h2f(acc[2*c+1][2], acc[2*c+1][3]);
#pragma unroll
            for (int nb = 0; nb < 4; nb++) {
                uint32_t v0, v1, v2, v3;
                uint32_t vd = (uint32_t)__cvta_generic_to_shared(
                    Vd + (c * 16 + (lane & 15)) * VH + nb * 16 + (lane >> 4) * 8);
                LDSM_X4T(v0, v1, v2, v3, vd);
                MMA_F16(oa[2*nb],   a0, a1, a2, a3, v0, v1);
                MMA_F16(oa[2*nb+1], a0, a1, a2, a3, v2, v3);
            }
        }

        if (kt + 1 < 32) {
            asm volatile("cp.async.wait_group 0;\n");
            __syncthreads();
        }
    }

    const float i0 = 1.f / l0, i1 = 1.f / l1;
    __half* ob = o + (size_t)(b * 2048 + qt * 128 + warp * 16 + lr) * OMLP_N + h * D_DIM;
#pragma unroll
    for (int dt = 0; dt < 8; dt++) {
        *(uint32_t*)(ob + dt * 8 + 2 * lc) =
            pack_h2f(oa[dt][0] * i0, oa[dt][1] * i0);
        *(uint32_t*)(ob + 8 * OMLP_N + dt * 8 + 2 * lc) =
            pack_h2f(oa[dt][2] * i1, oa[dt][3] * i1);
    }
}

// ---------------- gate = tanh(x @ W_g + b_g) ----------------
__global__ void __launch_bounds__(256) k_gate(
    const float* __restrict__ x, const float* __restrict__ Wg,
    const float* __restrict__ bg, float* __restrict__ gate)
{
    __shared__ float xs[1024];
    __shared__ float part[16][17];
    const int r = blockIdx.x, tid = threadIdx.x;
    *(float4*)&xs[tid * 4] = ((const float4*)(x + (size_t)r * C_DIM))[tid];
    __syncthreads();
    const int h = tid & 15, seg = tid >> 4;
    float s = 0.f;
#pragma unroll 8
    for (int c = seg * 64; c < seg * 64 + 64; c++) s += xs[c] * Wg[c * 16 + h];
    part[h][seg] = s;
    __syncthreads();
    if (tid < 16) {
        float t = bg[tid];
#pragma unroll
        for (int sg = 0; sg < 16; sg++) t += part[tid][sg];
        gate[(size_t)r * 16 + tid] = tanhf(t);
    }
}

// ---------------- rms[b,h] over (n,d) of f (half) ----------------
__global__ void __launch_bounds__(256) k_rms(const __half* __restrict__ f, float* __restrict__ rms)
{
    const int b = blockIdx.x >> 4, h = blockIdx.x & 15;
    float s = 0.f;
    for (int n = threadIdx.x; n < 2048; n += 256) {
        const __half2* fp = (const __half2*)(f + (size_t)(b * 2048 + n) * C_DIM + h * D_DIM);
#pragma unroll
        for (int d2 = 0; d2 < 32; d2++) {
            const float2 v = __half22float2(fp[d2]);
            s += v.x * v.x + v.y * v.y;
        }
    }
    s = block_reduce_sum(s);
    if (threadIdx.x == 0)
        rms[blockIdx.x] = fmaxf(sqrtf(s * (1.f / 131072.f)), 1e-6f);
}

// ---------------- o = half(o + gate * f / rms), o inside omlp --------------
__global__ void __launch_bounds__(256) k_combine(
    __half* __restrict__ o, const __half* __restrict__ f,
    const float* __restrict__ gate, const float* __restrict__ rms)
{
    const int r = blockIdx.x, tid = threadIdx.x;
    const int h = tid >> 4;
    const float g = gate[(size_t)r * 16 + h] / rms[(r >> 11) * 16 + h];
    __half2* op = (__half2*)(o + (size_t)r * OMLP_N) + tid * 2;
    const __half2* fp = (const __half2*)(f + (size_t)r * C_DIM) + tid * 2;
    const float2 f01 = __half22float2(fp[0]);
    const float2 f23 = __half22float2(fp[1]);
    float2 a = __half22float2(op[0]);
    float2 bq = __half22float2(op[1]);
    a.x += g * f01.x; a.y += g * f01.y;
    bq.x += g * f23.x; bq.y += g * f23.y;
    op[0] = __floats2half2_rn(a.x, a.y);
    op[1] = __floats2half2_rn(bq.x, bq.y);
}

// ---------------- launch ----------------
extern "C" void kernel_launch(void* const* d_in, const int* in_sizes, int n_in,
                              void* d_out, int out_size)
{
    const float* x     = (const float*)d_in[0];
    const float* emb   = (const float*)d_in[1];
    const float* W_emb = (const float*)d_in[2];
    const float* b_emb = (const float*)d_in[3];
    const float* ln_w  = (const float*)d_in[4];
    const float* ln_b  = (const float*)d_in[5];
    const float* W_f   = (const float*)d_in[6];
    const float* b_f   = (const float*)d_in[7];
    const float* qn_w  = (const float*)d_in[8];
    const float* qn_b  = (const float*)d_in[9];
    const float* kn_w  = (const float*)d_in[10];
    const float* kn_b  = (const float*)d_in[11];
    const float* W_ao  = (const float*)d_in[12];
    const float* b_ao  = (const float*)d_in[13];
    const float* W_mo  = (const float*)d_in[14];
    const float* b_mo  = (const float*)d_in[15];
    const float* Wm_in = (const float*)d_in[16];
    const float* bm_in = (const float*)d_in[17];
    const float* Wm_out= (const float*)d_in[18];
    const float* bm_out= (const float*)d_in[19];
    const float* W_g   = (const float*)d_in[20];
    const float* b_g   = (const float*)d_in[21];
    float* out = (float*)d_out;

    float *gate, *rms, *bmin, *bcomb;
    __half *se, *xn, *qkv, *omlp, *h2, *f;
    __half *embt, *Wembh, *Wfh, *Wminh, *Wmoh, *Wcomb;
    cudaGetSymbolAddress((void**)&se,    g_se);
    cudaGetSymbolAddress((void**)&xn,    g_xn);
    cudaGetSymbolAddress((void**)&qkv,   g_qkv);
    cudaGetSymbolAddress((void**)&omlp,  g_omlp);
    cudaGetSymbolAddress((void**)&h2,    g_h2);
    cudaGetSymbolAddress((void**)&f,     g_f);
    cudaGetSymbolAddress((void**)&gate,  g_gate);
    cudaGetSymbolAddress((void**)&rms,   g_rms);
    cudaGetSymbolAddress((void**)&embt,  g_embt);
    cudaGetSymbolAddress((void**)&Wembh, g_Wembh);
    cudaGetSymbolAddress((void**)&Wfh,   g_Wfh);
    cudaGetSymbolAddress((void**)&Wminh, g_Wminh);
    cudaGetSymbolAddress((void**)&bmin,  g_bmin);
    cudaGetSymbolAddress((void**)&Wmoh,  g_Wmoh);
    cudaGetSymbolAddress((void**)&Wcomb, g_Wcomb);
    cudaGetSymbolAddress((void**)&bcomb, g_bcomb);

    cudaFuncSetAttribute(tgemm_h<__half, false, 0>, cudaFuncAttributeMaxDynamicSharedMemorySize, GSMEM);
    cudaFuncSetAttribute(tgemm_h<__half, false, 2>, cudaFuncAttributeMaxDynamicSharedMemorySize, GSMEM);
    cudaFuncSetAttribute(tgemm_h<__half, false, 3>, cudaFuncAttributeMaxDynamicSharedMemorySize, GSMEM);
    cudaFuncSetAttribute(tgemm_h<float, true, 0>,   cudaFuncAttributeMaxDynamicSharedMemorySize, GSMEM);
    cudaFuncSetAttribute(k_attn_h, cudaFuncAttributeMaxDynamicSharedMemorySize, ATT_SMEM);

    const int MB = T_ROWS / 128;  // 64
    dim3 blk(256);

    // ---- merged operand prep ----
    CvtTasks tasks;
    int bs = 0;
    tasks.t[0] = { emb,    embt,  T_ROWS,  C_DIM,   C_DIM,   bs }; bs += T_ROWS  * (C_DIM   / 1024);
    tasks.t[1] = { W_emb,  Wembh, C_DIM,   SE_N,    SE_N,    bs }; bs += C_DIM   * (SE_N    / 1024);
    tasks.t[2] = { W_f,    Wfh,   C_DIM,   FUSED_N, FUSED_N, bs }; bs += C_DIM   * (FUSED_N / 1024);
    tasks.t[3] = { Wm_out, Wmoh,  INNER,   C_DIM,   C_DIM,   bs }; bs += INNER_P * (C_DIM   / 1024);
    tasks.t[4] = { W_ao,   Wcomb, C_DIM,   C_DIM,   C_DIM,   bs }; bs += C_DIM   * (C_DIM   / 1024);
    tasks.t[5] = { W_mo,   Wcomb + (size_t)C_DIM * C_DIM,
                           MLP_DIM, C_DIM, C_DIM,   bs }; bs += MLP_DIM * (C_DIM / 1024);
    k_cvt_all<<<dim3(bs), blk>>>(tasks);
    k_cvt_gluW4<<<dim3((VG_P / 4 + 255) / 256, C_DIM), blk>>>(Wm_in, Wminh);
    k_misc<<<dim3(26), blk>>>(bm_in, bmin, b_ao, b_mo, bcomb);

    // se = emb @ W_emb + b_emb  (half out)
    tgemm_h<__half, false, 0><<<dim3(SE_N / 128, MB), blk, GSMEM>>>(
        embt, C_DIM, Wembh, SE_N, b_emb, nullptr, 0, se, SE_N, C_DIM, nullptr, 0,
        nullptr, nullptr, nullptr, nullptr);

    // xn = LN(x)*(1+scale)+shift
    k_lnmod<<<T_ROWS, blk>>>(x, ln_w, ln_b, se, xn);

    // fused: q,k (LN'd) + v -> qkv ; mlps (silu) -> omlp cols [1024:5120)
    tgemm_h<__half, false, 3><<<dim3(FUSED_N / 128, MB), blk, GSMEM>>>(
        xn, C_DIM, Wfh, FUSED_N, b_f, nullptr, 0, qkv, QKV_N, C_DIM,
        omlp + C_DIM, OMLP_N, qn_w, qn_b, kn_w, kn_b);

    // flash attention -> omlp cols [0:1024)
    k_attn_h<<<dim3(16, 64), blk, ATT_SMEM>>>(qkv, omlp);

    // h2 = silu(g)*vv fused in GEMM epilogue (paired weights)
    tgemm_h<__half, false, 2><<<dim3(VG_P / 128, MB), blk, GSMEM>>>(
        qkv, QKV_N, Wminh, VG_P, bmin, nullptr, 0, h2, INNER_P, C_DIM, nullptr, 0,
        nullptr, nullptr, nullptr, nullptr);

    // f = h2 @ Wm_out + bm_out  (half out)
    tgemm_h<__half, false, 0><<<dim3(C_DIM / 128, MB), blk, GSMEM>>>(
        h2, INNER_P, Wmoh, C_DIM, bm_out, nullptr, 0, f, C_DIM, INNER_P, nullptr, 0,
        nullptr, nullptr, nullptr, nullptr);

    // gate, rms, combine (updates o-region of omlp in place)
    k_gate<<<T_ROWS, blk>>>(x, W_g, b_g, gate);
    k_rms<<<4 * H_DIM, blk>>>(f, rms);
    k_combine<<<T_ROWS, blk>>>(omlp, f, gate, rms);

    // out = x + [o|mlps] @ [W_ao;W_mo] + (b_ao+b_mo)   — fused K=5120
    tgemm_h<float, true, 0><<<dim3(C_DIM / 128, MB), blk, GSMEM>>>(
        omlp, OMLP_N, Wcomb, C_DIM, bcomb, x, C_DIM, out, C_DIM, OMLP_N, nullptr, 0,
        nullptr, nullptr, nullptr, nullptr);
}